// round 9
// baseline (speedup 1.0000x reference)
#include <cuda_runtime.h>
#include <cuda_bf16.h>
#include <cstdint>
#include <math.h>

#define NPTS 120000
#define NBLK 938   // ceil(120000/128)

// ------------------------- static device scratch ---------------------------
__device__ __nv_bfloat16 xp_hi[(size_t)NPTS * 128], xp_lo[(size_t)NPTS * 128];
__device__ __nv_bfloat16 ab_hi[2][(size_t)NPTS * 128], ab_lo[2][(size_t)NPTS * 128];
__device__ __nv_bfloat16 t_hi[2][(size_t)NPTS * 64],  t_lo[2][(size_t)NPTS * 64];
__device__ __nv_bfloat16 u_hi[2][(size_t)NPTS * 64],  u_lo[2][(size_t)NPTS * 64];

// preconverted weights, transposed to [n][k], split bf16 hi/lo
__device__ __nv_bfloat16 w1t_hi[49152],  w1t_lo[49152];    // 6 x [64n][128k]
__device__ __nv_bfloat16 wkt_hi[663552], wkt_lo[663552];   // 6 x 27 x [64n][64k]
__device__ __nv_bfloat16 w2t_hi[49152],  w2t_lo[49152];    // 6 x [128n][64k]
__device__ __nv_bfloat16 wft_hi[16384],  wft_lo[16384];    // [128n][128k]

// ------------------------------ helpers ------------------------------------
__device__ __forceinline__ uint32_t smem_u32(const void* p) {
    uint32_t a;
    asm("{ .reg .u64 t; cvta.to.shared.u64 t, %1; cvt.u32.u64 %0, t; }" : "=r"(a) : "l"(p));
    return a;
}
__device__ __forceinline__ uint32_t sw128(uint32_t off) { return off ^ ((off >> 3) & 0x70); }

__device__ __forceinline__ uint32_t packbf(float x, float y) {  // low=bf16(x), high=bf16(y)
    uint32_t r;
    asm("cvt.rn.bf16x2.f32 %0, %1, %2;" : "=r"(r) : "f"(y), "f"(x));
    return r;
}
__device__ __forceinline__ float lo2f(uint32_t p) { return __uint_as_float(p << 16); }
__device__ __forceinline__ float hi2f(uint32_t p) { return __uint_as_float(p & 0xFFFF0000u); }

__device__ __forceinline__ void cpasync16(uint32_t dst, const void* src, uint32_t zf) {
    asm volatile("cp.async.cg.shared.global [%0], [%1], 16, %2;"
                 :: "r"(dst), "l"(src), "r"(zf) : "memory");
}
#define CP_COMMIT() asm volatile("cp.async.commit_group;" ::: "memory")
#define CP_WAIT(n)  asm volatile("cp.async.wait_group %0;" :: "n"(n) : "memory")

__device__ __forceinline__ void ldm4(uint32_t r[4], uint32_t addr) {
    asm volatile("ldmatrix.sync.aligned.m8n8.x4.shared.b16 {%0,%1,%2,%3}, [%4];"
                 : "=r"(r[0]), "=r"(r[1]), "=r"(r[2]), "=r"(r[3]) : "r"(addr));
}
__device__ __forceinline__ void mma16816(float d[4], const uint32_t a[4],
                                         uint32_t b0, uint32_t b1) {
    asm volatile("mma.sync.aligned.m16n8k16.row.col.f32.bf16.bf16.f32 "
                 "{%0,%1,%2,%3}, {%4,%5,%6,%7}, {%8,%9}, {%0,%1,%2,%3};"
                 : "+f"(d[0]), "+f"(d[1]), "+f"(d[2]), "+f"(d[3])
                 : "r"(a[0]), "r"(a[1]), "r"(a[2]), "r"(a[3]), "r"(b0), "r"(b1));
}

// ---------------- K=64 chunk MMA, warp tile m32 x n32, all 4 ks -------------
__device__ __forceinline__ void mma_chunk32(float acc[2][4][4],
                                            uint32_t Ah, uint32_t Al,
                                            uint32_t Bh, uint32_t Bl,
                                            int m0, int n0w, int lane) {
    const int ar = lane & 15, ak = (lane >> 4) << 3;
    const int bn = (lane & 7) + ((lane & 16) ? 8 : 0), bk = ((lane >> 3) & 1) << 3;
#pragma unroll
    for (int ks = 0; ks < 4; ++ks) {
        uint32_t ah[2][4], al[2][4], bh[2][4], bl[2][4];
#pragma unroll
        for (int mt = 0; mt < 2; ++mt) {
            uint32_t off = sw128((uint32_t)((m0 + mt * 16 + ar) * 128 + (ks * 16 + ak) * 2));
            ldm4(ah[mt], Ah + off);
            ldm4(al[mt], Al + off);
        }
#pragma unroll
        for (int g = 0; g < 2; ++g) {
            uint32_t off = sw128((uint32_t)((n0w + g * 16 + bn) * 128 + (ks * 16 + bk) * 2));
            ldm4(bh[g], Bh + off);
            ldm4(bl[g], Bl + off);
        }
#pragma unroll
        for (int mt = 0; mt < 2; ++mt)
#pragma unroll
            for (int nt = 0; nt < 4; ++nt) {
                int g = nt >> 1, o = (nt & 1) << 1;
                mma16816(acc[mt][nt], ah[mt], bh[g][o], bh[g][o + 1]);
                mma16816(acc[mt][nt], ah[mt], bl[g][o], bl[g][o + 1]);
                mma16816(acc[mt][nt], al[mt], bh[g][o], bh[g][o + 1]);
            }
    }
}

// --------------------------- staging (256 threads) --------------------------
// A copy-stage: 128 rows from [p][ld] planes, plane pitch 16KB
__device__ __forceinline__ void stageA_planes(uint32_t Sa, const __nv_bfloat16* hi,
                                              const __nv_bfloat16* lo, int ld, int koff,
                                              int p0, int tid) {
    int row = tid >> 1, plane = tid & 1, p = p0 + row;
    const __nv_bfloat16* src = (plane ? lo : hi) + (size_t)(p < NPTS ? p : 0) * ld + koff;
    uint32_t zf = (p < NPTS) ? 16u : 0u;
    uint32_t base = Sa + (plane << 14);
#pragma unroll
    for (int j = 0; j < 8; ++j)
        cpasync16(base + sw128((uint32_t)(row * 128 + j * 16)), src + j * 8, zf);
}

// A gather-stage: 128 rows via nbr[:,kk], plane pitch 16KB
__device__ __forceinline__ void stageA_gather256(uint32_t Sa, const __nv_bfloat16* hi,
                                                 const __nv_bfloat16* lo,
                                                 const int* __restrict__ nbr,
                                                 int p0, int kk, int tid) {
    int row = tid >> 1, plane = tid & 1, p = p0 + row;
    int nb = (p < NPTS) ? __ldg(&nbr[(size_t)p * 27 + kk]) : -1;
    const __nv_bfloat16* src = (plane ? lo : hi) + (size_t)(nb < 0 ? 0 : nb) * 64;
    uint32_t zf = (nb >= 0) ? 16u : 0u;
    uint32_t base = Sa + (plane << 14);
#pragma unroll
    for (int j = 0; j < 8; ++j)
        cpasync16(base + sw128((uint32_t)(row * 128 + j * 16)), src + j * 8, zf);
}

// B copy-stage: 64 rows x 64k from [n][srcld] planes, plane pitch 8KB
__device__ __forceinline__ void stageB_rows(uint32_t Sb, const __nv_bfloat16* hi,
                                            const __nv_bfloat16* lo, int srcld,
                                            int koff, int tid) {
#pragma unroll
    for (int j = 0; j < 4; ++j) {
        int fl = tid + (j << 8);
        int plane = fl >> 9, r9 = fl & 511, n = r9 >> 3, jj = r9 & 7;
        const __nv_bfloat16* src = (plane ? lo : hi) + (size_t)n * srcld + koff + jj * 8;
        cpasync16(Sb + (plane << 13) + sw128((uint32_t)(n * 128 + jj * 16)), src, 16u);
    }
}

// relu + split epilogue into [p][ld] planes (m32 x n32 acc)
__device__ __forceinline__ void epi_planes(const float acc[2][4][4],
                                           __nv_bfloat16* ghi, __nv_bfloat16* glo,
                                           int ld, int colbase,
                                           int p0, int m0, int n0w, int lane) {
    int r0 = lane >> 2, c0 = (lane & 3) << 1;
#pragma unroll
    for (int mt = 0; mt < 2; ++mt)
#pragma unroll
        for (int nt = 0; nt < 4; ++nt)
#pragma unroll
            for (int h = 0; h < 2; ++h) {
                int p = p0 + m0 + mt * 16 + r0 + h * 8;
                if (p >= NPTS) continue;
                int col = colbase + n0w + nt * 8 + c0;
                float v0 = fmaxf(acc[mt][nt][h * 2 + 0], 0.f);
                float v1 = fmaxf(acc[mt][nt][h * 2 + 1], 0.f);
                uint32_t hv = packbf(v0, v1);
                uint32_t lv = packbf(v0 - lo2f(hv), v1 - hi2f(hv));
                *(uint32_t*)(ghi + (size_t)p * ld + col) = hv;
                *(uint32_t*)(glo + (size_t)p * ld + col) = lv;
            }
}

extern __shared__ char dsm[];
// stage layout (49152 B): Ah +0 (16K), Al +16K, Bh +32K (8K), Bl +40K (8K)
#define STG   49152
#define OF_AL 16384
#define OF_BH 32768
#define OF_BL 40960

// ------------------------- weight prep (once per graph) --------------------
__global__ void prep_w(const float* __restrict__ W1s, const float* __restrict__ Wks,
                       const float* __restrict__ W2s, const float* __restrict__ Wf) {
    int idx = blockIdx.x * 256 + threadIdx.x;
    float w;
    __nv_bfloat16 *dh, *dl;
    size_t d;
    if (idx < 49152) {
        int i = idx / 8192, r = idx % 8192, n = r / 128, k = r % 128;
        w = W1s[(size_t)i * 8192 + (size_t)k * 64 + n];
        dh = w1t_hi; dl = w1t_lo; d = (size_t)i * 8192 + n * 128 + k;
    } else if (idx < 712704) {
        int t = idx - 49152;
        int j = t / 4096, r = t % 4096, n = r / 64, k = r % 64;
        w = Wks[(size_t)j * 4096 + (size_t)k * 64 + n];
        dh = wkt_hi; dl = wkt_lo; d = (size_t)j * 4096 + n * 64 + k;
    } else if (idx < 761856) {
        int t = idx - 712704;
        int i = t / 8192, r = t % 8192, n = r / 64, k = r % 64;
        w = W2s[(size_t)i * 8192 + (size_t)k * 128 + n];
        dh = w2t_hi; dl = w2t_lo; d = (size_t)i * 8192 + n * 64 + k;
    } else if (idx < 778240) {
        int t = idx - 761856;
        int n = t / 128, k = t % 128;
        w = Wf[(size_t)k * 128 + n];
        dh = wft_hi; dl = wft_lo; d = (size_t)n * 128 + k;
    } else return;
    __nv_bfloat16 h = __float2bfloat16(w);
    dh[d] = h;
    dl[d] = __float2bfloat16(w - __bfloat162float(h));
}

__global__ void prep_x(const float* __restrict__ x) {
    size_t i4 = (size_t)blockIdx.x * 256 + threadIdx.x;
    if (i4 >= (size_t)NPTS * 128 / 4) return;
    float4 v = ((const float4*)x)[i4];
    uint32_t h01 = packbf(v.x, v.y), h23 = packbf(v.z, v.w);
    uint32_t l01 = packbf(v.x - lo2f(h01), v.y - hi2f(h01));
    uint32_t l23 = packbf(v.z - lo2f(h23), v.w - hi2f(h23));
    ((uint32_t*)xp_hi)[i4 * 2] = h01; ((uint32_t*)xp_hi)[i4 * 2 + 1] = h23;
    ((uint32_t*)xp_lo)[i4 * 2] = l01; ((uint32_t*)xp_lo)[i4 * 2 + 1] = l23;
}

// --------------------------------- conv ------------------------------------
// u[branch] = relu( sum_kk gather(t[branch], nbr[:,kk]) @ Wk[layer,kk] )
// M=128 tile, 256 thr, 8 warps = 4m x 2n, m32 x n32 each (no K-split).
// Double-buffered 48KB stages -> 96KB smem, ~78 regs -> 2 CTA/SM.
__global__ void __launch_bounds__(256, 2)
conv_kernel(const int* __restrict__ nbr, int unit) {
    uint32_t sb = smem_u32(dsm);
    int tid = threadIdx.x, lane = tid & 31, wid = tid >> 5;
    int p0 = blockIdx.x * 128;
    int branch = blockIdx.y;
    int layer = unit + 3 * branch;
    int m0 = (wid & 3) * 32, n0 = (wid >> 2) * 32;
    const __nv_bfloat16* th = t_hi[branch];
    const __nv_bfloat16* tl = t_lo[branch];
    const __nv_bfloat16* wh = wkt_hi + (size_t)layer * 27 * 4096;
    const __nv_bfloat16* wl = wkt_lo + (size_t)layer * 27 * 4096;
    float acc[2][4][4] = {};

    stageA_gather256(sb, th, tl, nbr, p0, 0, tid);
    stageB_rows(sb + OF_BH, wh, wl, 64, 0, tid);
    CP_COMMIT();

    for (int kk = 0; kk < 27; ++kk) {
        uint32_t S = sb + (uint32_t)(kk & 1) * STG;
        if (kk < 26) {
            uint32_t S2 = sb + (uint32_t)((kk + 1) & 1) * STG;
            stageA_gather256(S2, th, tl, nbr, p0, kk + 1, tid);
            stageB_rows(S2 + OF_BH, wh + (size_t)(kk + 1) * 4096,
                        wl + (size_t)(kk + 1) * 4096, 64, 0, tid);
            CP_COMMIT();
            CP_WAIT(1);
        } else {
            CP_WAIT(0);
        }
        __syncthreads();
        mma_chunk32(acc, S, S + OF_AL, S + OF_BH, S + OF_BL, m0, n0, lane);
        __syncthreads();
    }
    epi_planes(acc, u_hi[branch], u_lo[branch], 64, 0, p0, m0, n0, lane);
}

// ------------------------------ fc1 ----------------------------------------
// t[branch] = relu( src @ W1[layer] ), K=128 (2 chunks), N=64
__global__ void __launch_bounds__(256)
fc1_kernel(int unit) {
    uint32_t sb = smem_u32(dsm);
    int tid = threadIdx.x, lane = tid & 31, wid = tid >> 5;
    int p0 = blockIdx.x * 128;
    int branch = blockIdx.y;
    int layer = unit + 3 * branch;
    int m0 = (wid & 3) * 32, n0w = (wid >> 2) * 32;
    const __nv_bfloat16* sh = (unit == 0) ? xp_hi : ab_hi[branch];
    const __nv_bfloat16* sl = (unit == 0) ? xp_lo : ab_lo[branch];
    const __nv_bfloat16* wh = w1t_hi + (size_t)layer * 8192;
    const __nv_bfloat16* wl = w1t_lo + (size_t)layer * 8192;
    float acc[2][4][4] = {};

#pragma unroll
    for (int ck = 0; ck < 2; ++ck) {
        stageA_planes(sb, sh, sl, 128, ck * 64, p0, tid);
        stageB_rows(sb + OF_BH, wh, wl, 128, ck * 64, tid);
        CP_COMMIT();
        CP_WAIT(0);
        __syncthreads();
        mma_chunk32(acc, sb, sb + OF_AL, sb + OF_BH, sb + OF_BL, m0, n0w, lane);
        __syncthreads();
    }
    epi_planes(acc, t_hi[branch], t_lo[branch], 64, 0, p0, m0, n0w, lane);
}

// ------------------------------ fc2 ----------------------------------------
// ab[branch] = relu( u[branch] @ W2[layer] + res ), N=128 via blockIdx.y halves
__global__ void __launch_bounds__(256)
fc2_kernel(int unit) {
    uint32_t sb = smem_u32(dsm);
    int tid = threadIdx.x, lane = tid & 31, wid = tid >> 5;
    int p0 = blockIdx.x * 128, cb = blockIdx.y * 64;
    int branch = blockIdx.z;
    int layer = unit + 3 * branch;
    int m0 = (wid & 3) * 32, n0w = (wid >> 2) * 32;
    const __nv_bfloat16* rh = (unit == 0) ? xp_hi : ab_hi[branch];
    const __nv_bfloat16* rl = (unit == 0) ? xp_lo : ab_lo[branch];
    const __nv_bfloat16* wh = w2t_hi + (size_t)layer * 8192 + (size_t)cb * 64;
    const __nv_bfloat16* wl = w2t_lo + (size_t)layer * 8192 + (size_t)cb * 64;
    float acc[2][4][4] = {};

    stageA_planes(sb, u_hi[branch], u_lo[branch], 64, 0, p0, tid);
    stageB_rows(sb + OF_BH, wh, wl, 64, 0, tid);
    CP_COMMIT();
    CP_WAIT(0);
    __syncthreads();
    mma_chunk32(acc, sb, sb + OF_AL, sb + OF_BH, sb + OF_BL, m0, n0w, lane);

    __nv_bfloat16* oh = ab_hi[branch];
    __nv_bfloat16* ol = ab_lo[branch];
    int r0 = lane >> 2, c0 = (lane & 3) << 1;
#pragma unroll
    for (int mt = 0; mt < 2; ++mt)
#pragma unroll
        for (int nt = 0; nt < 4; ++nt)
#pragma unroll
            for (int h = 0; h < 2; ++h) {
                int p = p0 + m0 + mt * 16 + r0 + h * 8;
                if (p >= NPTS) continue;
                int col = cb + n0w + nt * 8 + c0;
                uint32_t rhv = *(const uint32_t*)(rh + (size_t)p * 128 + col);
                uint32_t rlv = *(const uint32_t*)(rl + (size_t)p * 128 + col);
                float v0 = fmaxf(acc[mt][nt][h * 2 + 0] + lo2f(rhv) + lo2f(rlv), 0.f);
                float v1 = fmaxf(acc[mt][nt][h * 2 + 1] + hi2f(rhv) + hi2f(rlv), 0.f);
                uint32_t hv = packbf(v0, v1);
                uint32_t lv = packbf(v0 - lo2f(hv), v1 - hi2f(hv));
                *(uint32_t*)(oh + (size_t)p * 128 + col) = hv;
                *(uint32_t*)(ol + (size_t)p * 128 + col) = lv;
            }
}

// ------------------------------ final --------------------------------------
// out = a * sigmoid(b @ Wf) + x, K=128 (2 chunks), N=128 via blockIdx.y
__global__ void __launch_bounds__(256)
final_kernel(const float* __restrict__ x, float* __restrict__ out) {
    uint32_t sb = smem_u32(dsm);
    int tid = threadIdx.x, lane = tid & 31, wid = tid >> 5;
    int p0 = blockIdx.x * 128, cb = blockIdx.y * 64;
    int m0 = (wid & 3) * 32, n0w = (wid >> 2) * 32;
    const __nv_bfloat16* wh = wft_hi + (size_t)cb * 128;
    const __nv_bfloat16* wl = wft_lo + (size_t)cb * 128;
    float acc[2][4][4] = {};

#pragma unroll
    for (int ck = 0; ck < 2; ++ck) {
        stageA_planes(sb, ab_hi[1], ab_lo[1], 128, ck * 64, p0, tid);
        stageB_rows(sb + OF_BH, wh, wl, 128, ck * 64, tid);
        CP_COMMIT();
        CP_WAIT(0);
        __syncthreads();
        mma_chunk32(acc, sb, sb + OF_AL, sb + OF_BH, sb + OF_BL, m0, n0w, lane);
        __syncthreads();
    }

    int r0 = lane >> 2, c0 = (lane & 3) << 1;
#pragma unroll
    for (int mt = 0; mt < 2; ++mt)
#pragma unroll
        for (int nt = 0; nt < 4; ++nt)
#pragma unroll
            for (int h = 0; h < 2; ++h) {
                int p = p0 + m0 + mt * 16 + r0 + h * 8;
                if (p >= NPTS) continue;
                int col = cb + n0w + nt * 8 + c0;
                uint32_t ahv = *(const uint32_t*)(ab_hi[0] + (size_t)p * 128 + col);
                uint32_t alv = *(const uint32_t*)(ab_lo[0] + (size_t)p * 128 + col);
                float a0 = lo2f(ahv) + lo2f(alv), a1 = hi2f(ahv) + hi2f(alv);
                float2 xv = *(const float2*)(x + (size_t)p * 128 + col);
                float g0 = acc[mt][nt][h * 2 + 0], g1 = acc[mt][nt][h * 2 + 1];
                float2 v;
                v.x = a0 * (1.f / (1.f + __expf(-g0))) + xv.x;
                v.y = a1 * (1.f / (1.f + __expf(-g1))) + xv.y;
                *(float2*)(out + (size_t)p * 128 + col) = v;
            }
}

// ---------------------------------------------------------------------------
extern "C" void kernel_launch(void* const* d_in, const int* in_sizes, int n_in,
                              void* d_out, int out_size) {
    const float* x   = (const float*)d_in[0];
    const float* W1s = (const float*)d_in[1];
    const float* Wks = (const float*)d_in[2];
    const float* W2s = (const float*)d_in[3];
    const float* Wf  = (const float*)d_in[4];
    const int*   nbr = (const int*)d_in[5];
    float*       out = (float*)d_out;

    const int SM_CONV = 2 * STG;   // 98304 (double-buffered) -> 2 CTA/SM
    const int SM_FC   = STG;       // 49152

    cudaFuncSetAttribute(conv_kernel,  cudaFuncAttributeMaxDynamicSharedMemorySize, SM_CONV);
    cudaFuncSetAttribute(fc1_kernel,   cudaFuncAttributeMaxDynamicSharedMemorySize, SM_FC);
    cudaFuncSetAttribute(fc2_kernel,   cudaFuncAttributeMaxDynamicSharedMemorySize, SM_FC);
    cudaFuncSetAttribute(final_kernel, cudaFuncAttributeMaxDynamicSharedMemorySize, SM_FC);

    prep_w<<<3040, 256>>>(W1s, Wks, W2s, Wf);
    prep_x<<<(NPTS * 128 / 4 + 255) / 256, 256>>>(x);

    dim3 blk256(256);
    dim3 gfc1(NBLK, 2), gconv(NBLK, 2), gfc2(NBLK, 2, 2), gfin(NBLK, 2);

    for (int i = 0; i < 3; ++i) {
        fc1_kernel<<<gfc1, blk256, SM_FC>>>(i);
        conv_kernel<<<gconv, blk256, SM_CONV>>>(nbr, i);
        fc2_kernel<<<gfc2, blk256, SM_FC>>>(i);
    }
    final_kernel<<<gfin, blk256, SM_FC>>>(x, out);
}

// round 10
// speedup vs baseline: 1.1207x; 1.1207x over previous
#include <cuda_runtime.h>
#include <cuda_bf16.h>
#include <cstdint>
#include <math.h>

#define NPTS 120000
#define NBLK 938   // ceil(120000/128)

// ------------------------- static device scratch ---------------------------
__device__ __nv_bfloat16 xp_hi[(size_t)NPTS * 128], xp_lo[(size_t)NPTS * 128];
__device__ __nv_bfloat16 ab_hi[2][(size_t)NPTS * 128], ab_lo[2][(size_t)NPTS * 128];
__device__ __nv_bfloat16 t_hi[2][(size_t)NPTS * 64],  t_lo[2][(size_t)NPTS * 64];
__device__ __nv_bfloat16 u_hi[2][(size_t)NPTS * 64],  u_lo[2][(size_t)NPTS * 64];

// preconverted weights, transposed to [n][k], split bf16 hi/lo
__device__ __nv_bfloat16 w1t_hi[49152],  w1t_lo[49152];    // 6 x [64n][128k]
__device__ __nv_bfloat16 wkt_hi[663552], wkt_lo[663552];   // 6 x 27 x [64n][64k]
__device__ __nv_bfloat16 w2t_hi[49152],  w2t_lo[49152];    // 6 x [128n][64k]
__device__ __nv_bfloat16 wft_hi[16384],  wft_lo[16384];    // [128n][128k]

// ------------------------------ helpers ------------------------------------
__device__ __forceinline__ uint32_t smem_u32(const void* p) {
    uint32_t a;
    asm("{ .reg .u64 t; cvta.to.shared.u64 t, %1; cvt.u32.u64 %0, t; }" : "=r"(a) : "l"(p));
    return a;
}
__device__ __forceinline__ uint32_t sw128(uint32_t off) { return off ^ ((off >> 3) & 0x70); }

__device__ __forceinline__ uint32_t packbf(float x, float y) {  // low=bf16(x), high=bf16(y)
    uint32_t r;
    asm("cvt.rn.bf16x2.f32 %0, %1, %2;" : "=r"(r) : "f"(y), "f"(x));
    return r;
}
__device__ __forceinline__ float lo2f(uint32_t p) { return __uint_as_float(p << 16); }
__device__ __forceinline__ float hi2f(uint32_t p) { return __uint_as_float(p & 0xFFFF0000u); }

__device__ __forceinline__ void cpasync16(uint32_t dst, const void* src, uint32_t zf) {
    asm volatile("cp.async.cg.shared.global [%0], [%1], 16, %2;"
                 :: "r"(dst), "l"(src), "r"(zf) : "memory");
}
#define CP_COMMIT() asm volatile("cp.async.commit_group;" ::: "memory")
#define CP_WAIT(n)  asm volatile("cp.async.wait_group %0;" :: "n"(n) : "memory")

__device__ __forceinline__ void ldm4(uint32_t r[4], uint32_t addr) {
    asm volatile("ldmatrix.sync.aligned.m8n8.x4.shared.b16 {%0,%1,%2,%3}, [%4];"
                 : "=r"(r[0]), "=r"(r[1]), "=r"(r[2]), "=r"(r[3]) : "r"(addr));
}
__device__ __forceinline__ void mma16816(float d[4], const uint32_t a[4],
                                         uint32_t b0, uint32_t b1) {
    asm volatile("mma.sync.aligned.m16n8k16.row.col.f32.bf16.bf16.f32 "
                 "{%0,%1,%2,%3}, {%4,%5,%6,%7}, {%8,%9}, {%0,%1,%2,%3};"
                 : "+f"(d[0]), "+f"(d[1]), "+f"(d[2]), "+f"(d[3])
                 : "r"(a[0]), "r"(a[1]), "r"(a[2]), "r"(a[3]), "r"(b0), "r"(b1));
}

// ---------------- K=64 chunk MMA, 8-warp variant (m32 x n32 / warp) ---------
__device__ __forceinline__ void mma_chunk32(float acc[2][4][4],
                                            uint32_t Ah, uint32_t Al,
                                            uint32_t Bh, uint32_t Bl,
                                            int m0, int n0w, int lane) {
    const int ar = lane & 15, ak = (lane >> 4) << 3;
    const int bn = (lane & 7) + ((lane & 16) ? 8 : 0), bk = ((lane >> 3) & 1) << 3;
#pragma unroll
    for (int ks = 0; ks < 4; ++ks) {
        uint32_t ah[2][4], al[2][4], bh[2][4], bl[2][4];
#pragma unroll
        for (int mt = 0; mt < 2; ++mt) {
            uint32_t off = sw128((uint32_t)((m0 + mt * 16 + ar) * 128 + (ks * 16 + ak) * 2));
            ldm4(ah[mt], Ah + off);
            ldm4(al[mt], Al + off);
        }
#pragma unroll
        for (int g = 0; g < 2; ++g) {
            uint32_t off = sw128((uint32_t)((n0w + g * 16 + bn) * 128 + (ks * 16 + bk) * 2));
            ldm4(bh[g], Bh + off);
            ldm4(bl[g], Bl + off);
        }
#pragma unroll
        for (int mt = 0; mt < 2; ++mt)
#pragma unroll
            for (int nt = 0; nt < 4; ++nt) {
                int g = nt >> 1, o = (nt & 1) << 1;
                mma16816(acc[mt][nt], ah[mt], bh[g][o], bh[g][o + 1]);
                mma16816(acc[mt][nt], ah[mt], bl[g][o], bl[g][o + 1]);
                mma16816(acc[mt][nt], al[mt], bh[g][o], bh[g][o + 1]);
            }
    }
}

// ---------------- K=64 chunk MMA, 16-warp variant (m32 x n16 / warp) --------
__device__ __forceinline__ void mma_chunk16(float acc[2][2][4],
                                            uint32_t Ah, uint32_t Al,
                                            uint32_t Bh, uint32_t Bl,
                                            int m0, int n0w, int lane) {
    const int ar = lane & 15, ak = (lane >> 4) << 3;
    const int bn = (lane & 7) + ((lane & 16) ? 8 : 0), bk = ((lane >> 3) & 1) << 3;
#pragma unroll
    for (int ks = 0; ks < 4; ++ks) {
        uint32_t ah[2][4], al[2][4], bh[4], bl[4];
#pragma unroll
        for (int mt = 0; mt < 2; ++mt) {
            uint32_t off = sw128((uint32_t)((m0 + mt * 16 + ar) * 128 + (ks * 16 + ak) * 2));
            ldm4(ah[mt], Ah + off);
            ldm4(al[mt], Al + off);
        }
        {
            uint32_t off = sw128((uint32_t)((n0w + bn) * 128 + (ks * 16 + bk) * 2));
            ldm4(bh, Bh + off);
            ldm4(bl, Bl + off);
        }
#pragma unroll
        for (int mt = 0; mt < 2; ++mt)
#pragma unroll
            for (int nt = 0; nt < 2; ++nt) {
                int o = nt << 1;
                mma16816(acc[mt][nt], ah[mt], bh[o], bh[o + 1]);
                mma16816(acc[mt][nt], ah[mt], bl[o], bl[o + 1]);
                mma16816(acc[mt][nt], al[mt], bh[o], bh[o + 1]);
            }
    }
}

// --------------------------- staging helpers -------------------------------
// A copy-stage (256 thr): rows p0..p0+127 from [p][ld] planes, cols koff..koff+63
__device__ __forceinline__ void stageA_planes(uint32_t Sa, const __nv_bfloat16* hi,
                                              const __nv_bfloat16* lo, int ld, int koff,
                                              int p0, int tid) {
    int row = tid >> 1, plane = tid & 1, p = p0 + row;
    const __nv_bfloat16* src = (plane ? lo : hi) + (size_t)(p < NPTS ? p : 0) * ld + koff;
    uint32_t zf = (p < NPTS) ? 16u : 0u;
    uint32_t base = Sa + (plane << 14);
#pragma unroll
    for (int j = 0; j < 8; ++j)
        cpasync16(base + sw128((uint32_t)(row * 128 + j * 16)), src + j * 8, zf);
}

// A gather-stage (512 thr): rows via nbr[:,kk], 64-col planes
__device__ __forceinline__ void stageA_gather512(uint32_t Sa, const __nv_bfloat16* hi,
                                                 const __nv_bfloat16* lo,
                                                 const int* __restrict__ nbr,
                                                 int p0, int kk, int tid) {
#pragma unroll
    for (int i = 0; i < 4; ++i) {
        int idx = tid + (i << 9);            // 0..2047
        int plane = idx >> 10, r10 = idx & 1023, row = r10 >> 3, j = r10 & 7;
        int p = p0 + row;
        int nb = (p < NPTS) ? __ldg(&nbr[(size_t)p * 27 + kk]) : -1;
        const __nv_bfloat16* src = (plane ? lo : hi) + (size_t)(nb < 0 ? 0 : nb) * 64 + j * 8;
        cpasync16(Sa + (plane << 14) + sw128((uint32_t)(row * 128 + j * 16)),
                  src, (nb >= 0) ? 16u : 0u);
    }
}

// B copy-stage, 256 thr: 64 rows x 64k from [n][srcld] planes at column koff
__device__ __forceinline__ void stageB_rows(uint32_t Sb, const __nv_bfloat16* hi,
                                            const __nv_bfloat16* lo, int srcld,
                                            int koff, int tid) {
#pragma unroll
    for (int j = 0; j < 4; ++j) {
        int fl = tid + (j << 8);
        int plane = fl >> 9, r9 = fl & 511, n = r9 >> 3, jj = r9 & 7;
        const __nv_bfloat16* src = (plane ? lo : hi) + (size_t)n * srcld + koff + jj * 8;
        cpasync16(Sb + (plane << 13) + sw128((uint32_t)(n * 128 + jj * 16)), src, 16u);
    }
}
// B copy-stage, 512 thr (srcld = 64)
__device__ __forceinline__ void stageB_rows512(uint32_t Sb, const __nv_bfloat16* hi,
                                               const __nv_bfloat16* lo, int tid) {
#pragma unroll
    for (int j = 0; j < 2; ++j) {
        int fl = tid + (j << 9);
        int plane = fl >> 9, r9 = fl & 511, n = r9 >> 3, jj = r9 & 7;
        const __nv_bfloat16* src = (plane ? lo : hi) + (size_t)n * 64 + jj * 8;
        cpasync16(Sb + (plane << 13) + sw128((uint32_t)(n * 128 + jj * 16)), src, 16u);
    }
}

// relu + split epilogue into [p][ld] planes (8-warp m32n32 variant)
__device__ __forceinline__ void epi_planes32(const float acc[2][4][4],
                                             __nv_bfloat16* ghi, __nv_bfloat16* glo,
                                             int ld, int colbase,
                                             int p0, int m0, int n0w, int lane) {
    int r0 = lane >> 2, c0 = (lane & 3) << 1;
#pragma unroll
    for (int mt = 0; mt < 2; ++mt)
#pragma unroll
        for (int nt = 0; nt < 4; ++nt)
#pragma unroll
            for (int h = 0; h < 2; ++h) {
                int p = p0 + m0 + mt * 16 + r0 + h * 8;
                if (p >= NPTS) continue;
                int col = colbase + n0w + nt * 8 + c0;
                float v0 = fmaxf(acc[mt][nt][h * 2 + 0], 0.f);
                float v1 = fmaxf(acc[mt][nt][h * 2 + 1], 0.f);
                uint32_t hv = packbf(v0, v1);
                uint32_t lv = packbf(v0 - lo2f(hv), v1 - hi2f(hv));
                *(uint32_t*)(ghi + (size_t)p * ld + col) = hv;
                *(uint32_t*)(glo + (size_t)p * ld + col) = lv;
            }
}

extern __shared__ char dsm[];
// conv stage layout (49152 B): Ah +0 (16K), Al +16K, Bh +32K (8K), Bl +40K (8K)
#define STG   49152
#define OF_AL 16384
#define OF_BH 32768
#define OF_BL 40960

// ------------------------- weight prep (once per graph) --------------------
__global__ void prep_w(const float* __restrict__ W1s, const float* __restrict__ Wks,
                       const float* __restrict__ W2s, const float* __restrict__ Wf) {
    int idx = blockIdx.x * 256 + threadIdx.x;
    float w;
    __nv_bfloat16 *dh, *dl;
    size_t d;
    if (idx < 49152) {
        int i = idx / 8192, r = idx % 8192, n = r / 128, k = r % 128;
        w = W1s[(size_t)i * 8192 + (size_t)k * 64 + n];
        dh = w1t_hi; dl = w1t_lo; d = (size_t)i * 8192 + n * 128 + k;
    } else if (idx < 712704) {
        int t = idx - 49152;
        int j = t / 4096, r = t % 4096, n = r / 64, k = r % 64;
        w = Wks[(size_t)j * 4096 + (size_t)k * 64 + n];
        dh = wkt_hi; dl = wkt_lo; d = (size_t)j * 4096 + n * 64 + k;
    } else if (idx < 761856) {
        int t = idx - 712704;
        int i = t / 8192, r = t % 8192, n = r / 64, k = r % 64;
        w = W2s[(size_t)i * 8192 + (size_t)k * 128 + n];
        dh = w2t_hi; dl = w2t_lo; d = (size_t)i * 8192 + n * 64 + k;
    } else if (idx < 778240) {
        int t = idx - 761856;
        int n = t / 128, k = t % 128;
        w = Wf[(size_t)k * 128 + n];
        dh = wft_hi; dl = wft_lo; d = (size_t)n * 128 + k;
    } else return;
    __nv_bfloat16 h = __float2bfloat16(w);
    dh[d] = h;
    dl[d] = __float2bfloat16(w - __bfloat162float(h));
}

// x -> split planes (once per graph)
__global__ void prep_x(const float* __restrict__ x) {
    size_t i4 = (size_t)blockIdx.x * 256 + threadIdx.x;
    if (i4 >= (size_t)NPTS * 128 / 4) return;
    float4 v = ((const float4*)x)[i4];
    uint32_t h01 = packbf(v.x, v.y), h23 = packbf(v.z, v.w);
    uint32_t l01 = packbf(v.x - lo2f(h01), v.y - hi2f(h01));
    uint32_t l23 = packbf(v.z - lo2f(h23), v.w - hi2f(h23));
    ((uint32_t*)xp_hi)[i4 * 2] = h01; ((uint32_t*)xp_hi)[i4 * 2 + 1] = h23;
    ((uint32_t*)xp_lo)[i4 * 2] = l01; ((uint32_t*)xp_lo)[i4 * 2 + 1] = l23;
}

// --------------------------------- conv ------------------------------------
// R5 config verbatim: 512 threads, 16 warps of m32 x n16 (4m x 4n),
// double-buffered 48KB stages -> 96KB, ptxas-capped 64 regs -> 2 CTA/SM.
__global__ void __launch_bounds__(512)
conv_kernel(const int* __restrict__ nbr, int unit) {
    uint32_t sb = smem_u32(dsm);
    int tid = threadIdx.x, lane = tid & 31, wid = tid >> 5;
    int p0 = blockIdx.x * 128;
    int branch = blockIdx.y;
    int layer = unit + 3 * branch;
    int m0 = (wid & 3) * 32, n0w = (wid >> 2) * 16;
    const __nv_bfloat16* th = t_hi[branch];
    const __nv_bfloat16* tl = t_lo[branch];
    const __nv_bfloat16* wh = wkt_hi + (size_t)layer * 27 * 4096;
    const __nv_bfloat16* wl = wkt_lo + (size_t)layer * 27 * 4096;
    float acc[2][2][4] = {};

    stageA_gather512(sb, th, tl, nbr, p0, 0, tid);
    stageB_rows512(sb + OF_BH, wh, wl, tid);
    CP_COMMIT();

    for (int kk = 0; kk < 27; ++kk) {
        uint32_t S = sb + (uint32_t)(kk & 1) * STG;
        if (kk < 26) {
            uint32_t S2 = sb + (uint32_t)((kk + 1) & 1) * STG;
            stageA_gather512(S2, th, tl, nbr, p0, kk + 1, tid);
            stageB_rows512(S2 + OF_BH, wh + (size_t)(kk + 1) * 4096,
                           wl + (size_t)(kk + 1) * 4096, tid);
            CP_COMMIT();
            CP_WAIT(1);
        } else {
            CP_WAIT(0);
        }
        __syncthreads();
        mma_chunk16(acc, S, S + OF_AL, S + OF_BH, S + OF_BL, m0, n0w, lane);
        __syncthreads();
    }

    // relu + split epilogue into u planes
    int r0 = lane >> 2, c0 = (lane & 3) << 1;
    __nv_bfloat16* uh = u_hi[branch];
    __nv_bfloat16* ul = u_lo[branch];
#pragma unroll
    for (int mt = 0; mt < 2; ++mt)
#pragma unroll
        for (int nt = 0; nt < 2; ++nt)
#pragma unroll
            for (int h = 0; h < 2; ++h) {
                int p = p0 + m0 + mt * 16 + r0 + h * 8;
                if (p >= NPTS) continue;
                int col = n0w + nt * 8 + c0;
                float v0 = fmaxf(acc[mt][nt][h * 2 + 0], 0.f);
                float v1 = fmaxf(acc[mt][nt][h * 2 + 1], 0.f);
                uint32_t hv = packbf(v0, v1);
                uint32_t lv = packbf(v0 - lo2f(hv), v1 - hi2f(hv));
                *(uint32_t*)(uh + (size_t)p * 64 + col) = hv;
                *(uint32_t*)(ul + (size_t)p * 64 + col) = lv;
            }
}

// ------------------------------ fc1 ----------------------------------------
// t[branch] = relu( src @ W1[layer] ), K=128 (2 chunks), N=64 (R5 verbatim)
__global__ void __launch_bounds__(256)
fc1_kernel(int unit) {
    uint32_t sb = smem_u32(dsm);
    int tid = threadIdx.x, lane = tid & 31, wid = tid >> 5;
    int p0 = blockIdx.x * 128;
    int branch = blockIdx.y;
    int layer = unit + 3 * branch;
    int m0 = (wid & 3) * 32, n0w = (wid >> 2) * 32;
    const __nv_bfloat16* sh = (unit == 0) ? xp_hi : ab_hi[branch];
    const __nv_bfloat16* sl = (unit == 0) ? xp_lo : ab_lo[branch];
    const __nv_bfloat16* wh = w1t_hi + (size_t)layer * 8192;
    const __nv_bfloat16* wl = w1t_lo + (size_t)layer * 8192;
    float acc[2][4][4] = {};

#pragma unroll
    for (int ck = 0; ck < 2; ++ck) {
        stageA_planes(sb, sh, sl, 128, ck * 64, p0, tid);
        stageB_rows(sb + OF_BH, wh, wl, 128, ck * 64, tid);
        CP_COMMIT();
        CP_WAIT(0);
        __syncthreads();
        mma_chunk32(acc, sb, sb + OF_AL, sb + OF_BH, sb + OF_BL, m0, n0w, lane);
        __syncthreads();
    }
    epi_planes32(acc, t_hi[branch], t_lo[branch], 64, 0, p0, m0, n0w, lane);
}

// ------------------------------ fc2 (merged N-halves) -----------------------
// ab[branch] = relu( u[branch] @ W2[layer] + res ), FULL N=128 per CTA.
// A (u planes) staged ONCE; both B halves staged upfront; two mma passes.
// smem 64KB -> 3 CTA/SM; grid (NBLK, 2).
__global__ void __launch_bounds__(256)
fc2_kernel(int unit) {
    uint32_t sb = smem_u32(dsm);
    int tid = threadIdx.x, lane = tid & 31, wid = tid >> 5;
    int p0 = blockIdx.x * 128;
    int branch = blockIdx.y;
    int layer = unit + 3 * branch;
    int m0 = (wid & 3) * 32, n0w = (wid >> 2) * 32;
    const __nv_bfloat16* rh = (unit == 0) ? xp_hi : ab_hi[branch];
    const __nv_bfloat16* rl = (unit == 0) ? xp_lo : ab_lo[branch];
    const __nv_bfloat16* wh = w2t_hi + (size_t)layer * 8192;   // [128n][64k]
    const __nv_bfloat16* wl = w2t_lo + (size_t)layer * 8192;

    // layout: Ah@0 Al@16K  B0h@32K B0l@40K  B1h@48K B1l@56K  (total 64K)
    stageA_planes(sb, u_hi[branch], u_lo[branch], 64, 0, p0, tid);
    stageB_rows(sb + 32768, wh, wl, 64, 0, tid);
    stageB_rows(sb + 49152, wh + 4096, wl + 4096, 64, 0, tid);
    CP_COMMIT();
    CP_WAIT(0);
    __syncthreads();

    __nv_bfloat16* oh = ab_hi[branch];
    __nv_bfloat16* ol = ab_lo[branch];
    int r0 = lane >> 2, c0 = (lane & 3) << 1;

#pragma unroll
    for (int half = 0; half < 2; ++half) {
        float acc[2][4][4] = {};
        uint32_t B = sb + 32768 + (uint32_t)half * 16384;
        mma_chunk32(acc, sb, sb + 16384, B, B + 8192, m0, n0w, lane);

        int cb = half * 64;
#pragma unroll
        for (int mt = 0; mt < 2; ++mt)
#pragma unroll
            for (int nt = 0; nt < 4; ++nt)
#pragma unroll
                for (int h = 0; h < 2; ++h) {
                    int p = p0 + m0 + mt * 16 + r0 + h * 8;
                    if (p >= NPTS) continue;
                    int col = cb + n0w + nt * 8 + c0;
                    uint32_t rhv = *(const uint32_t*)(rh + (size_t)p * 128 + col);
                    uint32_t rlv = *(const uint32_t*)(rl + (size_t)p * 128 + col);
                    float v0 = fmaxf(acc[mt][nt][h * 2 + 0] + lo2f(rhv) + lo2f(rlv), 0.f);
                    float v1 = fmaxf(acc[mt][nt][h * 2 + 1] + hi2f(rhv) + hi2f(rlv), 0.f);
                    uint32_t hv = packbf(v0, v1);
                    uint32_t lv = packbf(v0 - lo2f(hv), v1 - hi2f(hv));
                    *(uint32_t*)(oh + (size_t)p * 128 + col) = hv;
                    *(uint32_t*)(ol + (size_t)p * 128 + col) = lv;
                }
    }
}

// ------------------------------ final --------------------------------------
// out = a * sigmoid(b @ Wf) + x, K=128 (2 chunks), N=128 via blockIdx.y (R5)
__global__ void __launch_bounds__(256)
final_kernel(const float* __restrict__ x, float* __restrict__ out) {
    uint32_t sb = smem_u32(dsm);
    int tid = threadIdx.x, lane = tid & 31, wid = tid >> 5;
    int p0 = blockIdx.x * 128, cb = blockIdx.y * 64;
    int m0 = (wid & 3) * 32, n0w = (wid >> 2) * 32;
    const __nv_bfloat16* wh = wft_hi + (size_t)cb * 128;
    const __nv_bfloat16* wl = wft_lo + (size_t)cb * 128;
    float acc[2][4][4] = {};

#pragma unroll
    for (int ck = 0; ck < 2; ++ck) {
        stageA_planes(sb, ab_hi[1], ab_lo[1], 128, ck * 64, p0, tid);
        stageB_rows(sb + OF_BH, wh, wl, 128, ck * 64, tid);
        CP_COMMIT();
        CP_WAIT(0);
        __syncthreads();
        mma_chunk32(acc, sb, sb + OF_AL, sb + OF_BH, sb + OF_BL, m0, n0w, lane);
        __syncthreads();
    }

    int r0 = lane >> 2, c0 = (lane & 3) << 1;
#pragma unroll
    for (int mt = 0; mt < 2; ++mt)
#pragma unroll
        for (int nt = 0; nt < 4; ++nt)
#pragma unroll
            for (int h = 0; h < 2; ++h) {
                int p = p0 + m0 + mt * 16 + r0 + h * 8;
                if (p >= NPTS) continue;
                int col = cb + n0w + nt * 8 + c0;
                uint32_t ahv = *(const uint32_t*)(ab_hi[0] + (size_t)p * 128 + col);
                uint32_t alv = *(const uint32_t*)(ab_lo[0] + (size_t)p * 128 + col);
                float a0 = lo2f(ahv) + lo2f(alv), a1 = hi2f(ahv) + hi2f(alv);
                float2 xv = *(const float2*)(x + (size_t)p * 128 + col);
                float g0 = acc[mt][nt][h * 2 + 0], g1 = acc[mt][nt][h * 2 + 1];
                float2 v;
                v.x = a0 * (1.f / (1.f + __expf(-g0))) + xv.x;
                v.y = a1 * (1.f / (1.f + __expf(-g1))) + xv.y;
                *(float2*)(out + (size_t)p * 128 + col) = v;
            }
}

// ---------------------------------------------------------------------------
extern "C" void kernel_launch(void* const* d_in, const int* in_sizes, int n_in,
                              void* d_out, int out_size) {
    const float* x   = (const float*)d_in[0];
    const float* W1s = (const float*)d_in[1];
    const float* Wks = (const float*)d_in[2];
    const float* W2s = (const float*)d_in[3];
    const float* Wf  = (const float*)d_in[4];
    const int*   nbr = (const int*)d_in[5];
    float*       out = (float*)d_out;

    const int SM_CONV = 2 * STG;   // 98304 (double-buffered) -> 2 CTA/SM
    const int SM_FC   = STG;       // 49152
    const int SM_FC2  = 65536;     // A + both B halves -> 3 CTA/SM

    cudaFuncSetAttribute(conv_kernel,  cudaFuncAttributeMaxDynamicSharedMemorySize, SM_CONV);
    cudaFuncSetAttribute(fc1_kernel,   cudaFuncAttributeMaxDynamicSharedMemorySize, SM_FC);
    cudaFuncSetAttribute(fc2_kernel,   cudaFuncAttributeMaxDynamicSharedMemorySize, SM_FC2);
    cudaFuncSetAttribute(final_kernel, cudaFuncAttributeMaxDynamicSharedMemorySize, SM_FC);

    prep_w<<<3040, 256>>>(W1s, Wks, W2s, Wf);
    prep_x<<<(NPTS * 128 / 4 + 255) / 256, 256>>>(x);

    dim3 blk256(256), blk512(512);
    dim3 gfc1(NBLK, 2), gconv(NBLK, 2), gfc2(NBLK, 2), gfin(NBLK, 2);

    for (int i = 0; i < 3; ++i) {
        fc1_kernel<<<gfc1, blk256, SM_FC>>>(i);
        conv_kernel<<<gconv, blk512, SM_CONV>>>(nbr, i);
        fc2_kernel<<<gfc2, blk256, SM_FC2>>>(i);
    }
    final_kernel<<<gfin, blk256, SM_FC>>>(x, out);
}

// round 11
// speedup vs baseline: 1.1880x; 1.0601x over previous
#include <cuda_runtime.h>
#include <cuda_bf16.h>
#include <cstdint>
#include <math.h>

#define NPTS 120000
#define NBLK 938   // ceil(120000/128)

// ------------------------- static device scratch ---------------------------
__device__ __nv_bfloat16 xp_hi[(size_t)NPTS * 128], xp_lo[(size_t)NPTS * 128];
__device__ __nv_bfloat16 ab_hi[2][(size_t)NPTS * 128], ab_lo[2][(size_t)NPTS * 128];
__device__ __nv_bfloat16 t_hi[2][(size_t)NPTS * 64],  t_lo[2][(size_t)NPTS * 64];

// preconverted weights, transposed to [n][k], split bf16 hi/lo
__device__ __nv_bfloat16 w1t_hi[49152],  w1t_lo[49152];    // 6 x [64n][128k]
__device__ __nv_bfloat16 wkt_hi[663552], wkt_lo[663552];   // 6 x 27 x [64n][64k]
__device__ __nv_bfloat16 w2t_hi[49152],  w2t_lo[49152];    // 6 x [128n][64k]
__device__ __nv_bfloat16 wft_hi[16384],  wft_lo[16384];    // [128n][128k]

// ------------------------------ helpers ------------------------------------
__device__ __forceinline__ uint32_t smem_u32(const void* p) {
    uint32_t a;
    asm("{ .reg .u64 t; cvta.to.shared.u64 t, %1; cvt.u32.u64 %0, t; }" : "=r"(a) : "l"(p));
    return a;
}
__device__ __forceinline__ uint32_t sw128(uint32_t off) { return off ^ ((off >> 3) & 0x70); }

__device__ __forceinline__ uint32_t packbf(float x, float y) {  // low=bf16(x), high=bf16(y)
    uint32_t r;
    asm("cvt.rn.bf16x2.f32 %0, %1, %2;" : "=r"(r) : "f"(y), "f"(x));
    return r;
}
__device__ __forceinline__ float lo2f(uint32_t p) { return __uint_as_float(p << 16); }
__device__ __forceinline__ float hi2f(uint32_t p) { return __uint_as_float(p & 0xFFFF0000u); }

__device__ __forceinline__ void sts32(uint32_t a, uint32_t v) {
    asm volatile("st.shared.b32 [%0], %1;" :: "r"(a), "r"(v) : "memory");
}
__device__ __forceinline__ void cpasync16(uint32_t dst, const void* src, uint32_t zf) {
    asm volatile("cp.async.cg.shared.global [%0], [%1], 16, %2;"
                 :: "r"(dst), "l"(src), "r"(zf) : "memory");
}
#define CP_COMMIT() asm volatile("cp.async.commit_group;" ::: "memory")
#define CP_WAIT(n)  asm volatile("cp.async.wait_group %0;" :: "n"(n) : "memory")

__device__ __forceinline__ void ldm4(uint32_t r[4], uint32_t addr) {
    asm volatile("ldmatrix.sync.aligned.m8n8.x4.shared.b16 {%0,%1,%2,%3}, [%4];"
                 : "=r"(r[0]), "=r"(r[1]), "=r"(r[2]), "=r"(r[3]) : "r"(addr));
}
__device__ __forceinline__ void mma16816(float d[4], const uint32_t a[4],
                                         uint32_t b0, uint32_t b1) {
    asm volatile("mma.sync.aligned.m16n8k16.row.col.f32.bf16.bf16.f32 "
                 "{%0,%1,%2,%3}, {%4,%5,%6,%7}, {%8,%9}, {%0,%1,%2,%3};"
                 : "+f"(d[0]), "+f"(d[1]), "+f"(d[2]), "+f"(d[3])
                 : "r"(a[0]), "r"(a[1]), "r"(a[2]), "r"(a[3]), "r"(b0), "r"(b1));
}

// ---------------- K=64 chunk MMA, 8-warp variant (m32 x n32 / warp) ---------
__device__ __forceinline__ void mma_chunk32(float acc[2][4][4],
                                            uint32_t Ah, uint32_t Al,
                                            uint32_t Bh, uint32_t Bl,
                                            int m0, int n0w, int lane) {
    const int ar = lane & 15, ak = (lane >> 4) << 3;
    const int bn = (lane & 7) + ((lane & 16) ? 8 : 0), bk = ((lane >> 3) & 1) << 3;
#pragma unroll
    for (int ks = 0; ks < 4; ++ks) {
        uint32_t ah[2][4], al[2][4], bh[2][4], bl[2][4];
#pragma unroll
        for (int mt = 0; mt < 2; ++mt) {
            uint32_t off = sw128((uint32_t)((m0 + mt * 16 + ar) * 128 + (ks * 16 + ak) * 2));
            ldm4(ah[mt], Ah + off);
            ldm4(al[mt], Al + off);
        }
#pragma unroll
        for (int g = 0; g < 2; ++g) {
            uint32_t off = sw128((uint32_t)((n0w + g * 16 + bn) * 128 + (ks * 16 + bk) * 2));
            ldm4(bh[g], Bh + off);
            ldm4(bl[g], Bl + off);
        }
#pragma unroll
        for (int mt = 0; mt < 2; ++mt)
#pragma unroll
            for (int nt = 0; nt < 4; ++nt) {
                int g = nt >> 1, o = (nt & 1) << 1;
                mma16816(acc[mt][nt], ah[mt], bh[g][o], bh[g][o + 1]);
                mma16816(acc[mt][nt], ah[mt], bl[g][o], bl[g][o + 1]);
                mma16816(acc[mt][nt], al[mt], bh[g][o], bh[g][o + 1]);
            }
    }
}

// ---------------- K=64 chunk MMA, 16-warp variant (m32 x n16 / warp) --------
__device__ __forceinline__ void mma_chunk16(float acc[2][2][4],
                                            uint32_t Ah, uint32_t Al,
                                            uint32_t Bh, uint32_t Bl,
                                            int m0, int n0w, int lane) {
    const int ar = lane & 15, ak = (lane >> 4) << 3;
    const int bn = (lane & 7) + ((lane & 16) ? 8 : 0), bk = ((lane >> 3) & 1) << 3;
#pragma unroll
    for (int ks = 0; ks < 4; ++ks) {
        uint32_t ah[2][4], al[2][4], bh[4], bl[4];
#pragma unroll
        for (int mt = 0; mt < 2; ++mt) {
            uint32_t off = sw128((uint32_t)((m0 + mt * 16 + ar) * 128 + (ks * 16 + ak) * 2));
            ldm4(ah[mt], Ah + off);
            ldm4(al[mt], Al + off);
        }
        {
            uint32_t off = sw128((uint32_t)((n0w + bn) * 128 + (ks * 16 + bk) * 2));
            ldm4(bh, Bh + off);
            ldm4(bl, Bl + off);
        }
#pragma unroll
        for (int mt = 0; mt < 2; ++mt)
#pragma unroll
            for (int nt = 0; nt < 2; ++nt) {
                int o = nt << 1;
                mma16816(acc[mt][nt], ah[mt], bh[o], bh[o + 1]);
                mma16816(acc[mt][nt], ah[mt], bl[o], bl[o + 1]);
                mma16816(acc[mt][nt], al[mt], bh[o], bh[o + 1]);
            }
    }
}

// --------------------------- staging helpers -------------------------------
// A copy-stage (256 thr): rows p0..p0+127 from [p][ld] planes, cols koff..koff+63
__device__ __forceinline__ void stageA_planes(uint32_t Sa, const __nv_bfloat16* hi,
                                              const __nv_bfloat16* lo, int ld, int koff,
                                              int p0, int tid) {
    int row = tid >> 1, plane = tid & 1, p = p0 + row;
    const __nv_bfloat16* src = (plane ? lo : hi) + (size_t)(p < NPTS ? p : 0) * ld + koff;
    uint32_t zf = (p < NPTS) ? 16u : 0u;
    uint32_t base = Sa + (plane << 14);
#pragma unroll
    for (int j = 0; j < 8; ++j)
        cpasync16(base + sw128((uint32_t)(row * 128 + j * 16)), src + j * 8, zf);
}

// A gather-stage (512 thr): rows via nbr[:,kk], 64-col planes
__device__ __forceinline__ void stageA_gather512(uint32_t Sa, const __nv_bfloat16* hi,
                                                 const __nv_bfloat16* lo,
                                                 const int* __restrict__ nbr,
                                                 int p0, int kk, int tid) {
#pragma unroll
    for (int i = 0; i < 4; ++i) {
        int idx = tid + (i << 9);            // 0..2047
        int plane = idx >> 10, r10 = idx & 1023, row = r10 >> 3, j = r10 & 7;
        int p = p0 + row;
        int nb = (p < NPTS) ? __ldg(&nbr[(size_t)p * 27 + kk]) : -1;
        const __nv_bfloat16* src = (plane ? lo : hi) + (size_t)(nb < 0 ? 0 : nb) * 64 + j * 8;
        cpasync16(Sa + (plane << 14) + sw128((uint32_t)(row * 128 + j * 16)),
                  src, (nb >= 0) ? 16u : 0u);
    }
}

// B copy-stage, 256 thr: 64 rows x 64k from [n][srcld] planes at column koff
__device__ __forceinline__ void stageB_rows(uint32_t Sb, const __nv_bfloat16* hi,
                                            const __nv_bfloat16* lo, int srcld,
                                            int koff, int tid) {
#pragma unroll
    for (int j = 0; j < 4; ++j) {
        int fl = tid + (j << 8);
        int plane = fl >> 9, r9 = fl & 511, n = r9 >> 3, jj = r9 & 7;
        const __nv_bfloat16* src = (plane ? lo : hi) + (size_t)n * srcld + koff + jj * 8;
        cpasync16(Sb + (plane << 13) + sw128((uint32_t)(n * 128 + jj * 16)), src, 16u);
    }
}
// B copy-stage, 512 thr (srcld = 64)
__device__ __forceinline__ void stageB_rows512(uint32_t Sb, const __nv_bfloat16* hi,
                                               const __nv_bfloat16* lo, int tid) {
#pragma unroll
    for (int j = 0; j < 2; ++j) {
        int fl = tid + (j << 9);
        int plane = fl >> 9, r9 = fl & 511, n = r9 >> 3, jj = r9 & 7;
        const __nv_bfloat16* src = (plane ? lo : hi) + (size_t)n * 64 + jj * 8;
        cpasync16(Sb + (plane << 13) + sw128((uint32_t)(n * 128 + jj * 16)), src, 16u);
    }
}

// relu + split epilogue into [p][ld] planes (8-warp m32n32 variant)
__device__ __forceinline__ void epi_planes32(const float acc[2][4][4],
                                             __nv_bfloat16* ghi, __nv_bfloat16* glo,
                                             int ld, int colbase,
                                             int p0, int m0, int n0w, int lane) {
    int r0 = lane >> 2, c0 = (lane & 3) << 1;
#pragma unroll
    for (int mt = 0; mt < 2; ++mt)
#pragma unroll
        for (int nt = 0; nt < 4; ++nt)
#pragma unroll
            for (int h = 0; h < 2; ++h) {
                int p = p0 + m0 + mt * 16 + r0 + h * 8;
                if (p >= NPTS) continue;
                int col = colbase + n0w + nt * 8 + c0;
                float v0 = fmaxf(acc[mt][nt][h * 2 + 0], 0.f);
                float v1 = fmaxf(acc[mt][nt][h * 2 + 1], 0.f);
                uint32_t hv = packbf(v0, v1);
                uint32_t lv = packbf(v0 - lo2f(hv), v1 - hi2f(hv));
                *(uint32_t*)(ghi + (size_t)p * ld + col) = hv;
                *(uint32_t*)(glo + (size_t)p * ld + col) = lv;
            }
}

extern __shared__ char dsm[];
// conv stage layout (49152 B): Ah +0 (16K), Al +16K, Bh +32K (8K), Bl +40K (8K)
#define STG   49152
#define OF_AL 16384
#define OF_BH 32768
#define OF_BL 40960

// ------------------------- weight prep (once per graph) --------------------
__global__ void prep_w(const float* __restrict__ W1s, const float* __restrict__ Wks,
                       const float* __restrict__ W2s, const float* __restrict__ Wf) {
    int idx = blockIdx.x * 256 + threadIdx.x;
    float w;
    __nv_bfloat16 *dh, *dl;
    size_t d;
    if (idx < 49152) {
        int i = idx / 8192, r = idx % 8192, n = r / 128, k = r % 128;
        w = W1s[(size_t)i * 8192 + (size_t)k * 64 + n];
        dh = w1t_hi; dl = w1t_lo; d = (size_t)i * 8192 + n * 128 + k;
    } else if (idx < 712704) {
        int t = idx - 49152;
        int j = t / 4096, r = t % 4096, n = r / 64, k = r % 64;
        w = Wks[(size_t)j * 4096 + (size_t)k * 64 + n];
        dh = wkt_hi; dl = wkt_lo; d = (size_t)j * 4096 + n * 64 + k;
    } else if (idx < 761856) {
        int t = idx - 712704;
        int i = t / 8192, r = t % 8192, n = r / 64, k = r % 64;
        w = W2s[(size_t)i * 8192 + (size_t)k * 128 + n];
        dh = w2t_hi; dl = w2t_lo; d = (size_t)i * 8192 + n * 64 + k;
    } else if (idx < 778240) {
        int t = idx - 761856;
        int n = t / 128, k = t % 128;
        w = Wf[(size_t)k * 128 + n];
        dh = wft_hi; dl = wft_lo; d = (size_t)n * 128 + k;
    } else return;
    __nv_bfloat16 h = __float2bfloat16(w);
    dh[d] = h;
    dl[d] = __float2bfloat16(w - __bfloat162float(h));
}

// x -> split planes (once per graph)
__global__ void prep_x(const float* __restrict__ x) {
    size_t i4 = (size_t)blockIdx.x * 256 + threadIdx.x;
    if (i4 >= (size_t)NPTS * 128 / 4) return;
    float4 v = ((const float4*)x)[i4];
    uint32_t h01 = packbf(v.x, v.y), h23 = packbf(v.z, v.w);
    uint32_t l01 = packbf(v.x - lo2f(h01), v.y - hi2f(h01));
    uint32_t l23 = packbf(v.z - lo2f(h23), v.w - hi2f(h23));
    ((uint32_t*)xp_hi)[i4 * 2] = h01; ((uint32_t*)xp_hi)[i4 * 2 + 1] = h23;
    ((uint32_t*)xp_lo)[i4 * 2] = l01; ((uint32_t*)xp_lo)[i4 * 2 + 1] = l23;
}

// ----------------------- conv + fused fc2 -----------------------------------
// Mainloop (R5 config, 512 thr, 16 warps m32xn16): u = relu(conv3(t[branch])).
// Epilogue: u fragments -> smem planes; two N=64 fc2 passes:
//   ab[branch] = relu( u @ W2[layer] + res ),  res = xp (unit 0) or ab[branch].
// u never touches global memory.
__global__ void __launch_bounds__(512, 2)
conv_fc2_kernel(const int* __restrict__ nbr, int unit) {
    uint32_t sb = smem_u32(dsm);
    int tid = threadIdx.x, lane = tid & 31, wid = tid >> 5;
    int p0 = blockIdx.x * 128;
    int branch = blockIdx.y;
    int layer = unit + 3 * branch;
    int m0 = (wid & 3) * 32, n0w = (wid >> 2) * 16;
    const __nv_bfloat16* th = t_hi[branch];
    const __nv_bfloat16* tl = t_lo[branch];
    const __nv_bfloat16* wh = wkt_hi + (size_t)layer * 27 * 4096;
    const __nv_bfloat16* wl = wkt_lo + (size_t)layer * 27 * 4096;
    float acc[2][2][4] = {};

    stageA_gather512(sb, th, tl, nbr, p0, 0, tid);
    stageB_rows512(sb + OF_BH, wh, wl, tid);
    CP_COMMIT();

    for (int kk = 0; kk < 27; ++kk) {
        uint32_t S = sb + (uint32_t)(kk & 1) * STG;
        if (kk < 26) {
            uint32_t S2 = sb + (uint32_t)((kk + 1) & 1) * STG;
            stageA_gather512(S2, th, tl, nbr, p0, kk + 1, tid);
            stageB_rows512(S2 + OF_BH, wh + (size_t)(kk + 1) * 4096,
                           wl + (size_t)(kk + 1) * 4096, tid);
            CP_COMMIT();
            CP_WAIT(1);
        } else {
            CP_WAIT(0);
        }
        __syncthreads();
        mma_chunk16(acc, S, S + OF_AL, S + OF_BH, S + OF_BL, m0, n0w, lane);
        __syncthreads();
    }

    // ---- write u tile (relu + split) into smem planes at buffer 0 ----
    int r0 = lane >> 2, c0 = (lane & 3) << 1;
#pragma unroll
    for (int mt = 0; mt < 2; ++mt)
#pragma unroll
        for (int nt = 0; nt < 2; ++nt)
#pragma unroll
            for (int h = 0; h < 2; ++h) {
                int row = m0 + mt * 16 + r0 + h * 8;
                int col = n0w + nt * 8 + c0;
                float v0 = fmaxf(acc[mt][nt][h * 2 + 0], 0.f);
                float v1 = fmaxf(acc[mt][nt][h * 2 + 1], 0.f);
                uint32_t hv = packbf(v0, v1);
                uint32_t lv = packbf(v0 - lo2f(hv), v1 - hi2f(hv));
                uint32_t off = sw128((uint32_t)(row * 128 + col * 2));
                sts32(sb + off, hv);
                sts32(sb + OF_AL + off, lv);
            }

    // ---- stage both W2 N-halves into buffer 1 ----
    const __nv_bfloat16* w2h = w2t_hi + (size_t)layer * 8192;   // [128n][64k]
    const __nv_bfloat16* w2l = w2t_lo + (size_t)layer * 8192;
    stageB_rows512(sb + STG,         w2h,        w2l,        tid);
    stageB_rows512(sb + STG + 16384, w2h + 4096, w2l + 4096, tid);
    CP_COMMIT();
    CP_WAIT(0);
    __syncthreads();

    // ---- fc2: two N=64 passes over the smem u tile ----
    const __nv_bfloat16* rh = (unit == 0) ? xp_hi : ab_hi[branch];
    const __nv_bfloat16* rl = (unit == 0) ? xp_lo : ab_lo[branch];
    __nv_bfloat16* oh = ab_hi[branch];
    __nv_bfloat16* ol = ab_lo[branch];

#pragma unroll
    for (int half = 0; half < 2; ++half) {
        float a2[2][2][4] = {};
        uint32_t B = sb + STG + (uint32_t)half * 16384;
        mma_chunk16(a2, sb, sb + OF_AL, B, B + 8192, m0, n0w, lane);

        int cb = half * 64;
#pragma unroll
        for (int mt = 0; mt < 2; ++mt)
#pragma unroll
            for (int nt = 0; nt < 2; ++nt)
#pragma unroll
                for (int h = 0; h < 2; ++h) {
                    int p = p0 + m0 + mt * 16 + r0 + h * 8;
                    if (p >= NPTS) continue;
                    int col = cb + n0w + nt * 8 + c0;
                    uint32_t rhv = *(const uint32_t*)(rh + (size_t)p * 128 + col);
                    uint32_t rlv = *(const uint32_t*)(rl + (size_t)p * 128 + col);
                    float v0 = fmaxf(a2[mt][nt][h * 2 + 0] + lo2f(rhv) + lo2f(rlv), 0.f);
                    float v1 = fmaxf(a2[mt][nt][h * 2 + 1] + hi2f(rhv) + hi2f(rlv), 0.f);
                    uint32_t hv = packbf(v0, v1);
                    uint32_t lv = packbf(v0 - lo2f(hv), v1 - hi2f(hv));
                    *(uint32_t*)(oh + (size_t)p * 128 + col) = hv;
                    *(uint32_t*)(ol + (size_t)p * 128 + col) = lv;
                }
    }
}

// ------------------------------ fc1 ----------------------------------------
// t[branch] = relu( src @ W1[layer] ), K=128 (2 chunks), N=64
__global__ void __launch_bounds__(256)
fc1_kernel(int unit) {
    uint32_t sb = smem_u32(dsm);
    int tid = threadIdx.x, lane = tid & 31, wid = tid >> 5;
    int p0 = blockIdx.x * 128;
    int branch = blockIdx.y;
    int layer = unit + 3 * branch;
    int m0 = (wid & 3) * 32, n0w = (wid >> 2) * 32;
    const __nv_bfloat16* sh = (unit == 0) ? xp_hi : ab_hi[branch];
    const __nv_bfloat16* sl = (unit == 0) ? xp_lo : ab_lo[branch];
    const __nv_bfloat16* wh = w1t_hi + (size_t)layer * 8192;
    const __nv_bfloat16* wl = w1t_lo + (size_t)layer * 8192;
    float acc[2][4][4] = {};

#pragma unroll
    for (int ck = 0; ck < 2; ++ck) {
        stageA_planes(sb, sh, sl, 128, ck * 64, p0, tid);
        stageB_rows(sb + OF_BH, wh, wl, 128, ck * 64, tid);
        CP_COMMIT();
        CP_WAIT(0);
        __syncthreads();
        mma_chunk32(acc, sb, sb + OF_AL, sb + OF_BH, sb + OF_BL, m0, n0w, lane);
        __syncthreads();
    }
    epi_planes32(acc, t_hi[branch], t_lo[branch], 64, 0, p0, m0, n0w, lane);
}

// ------------------------------ final --------------------------------------
// out = a * sigmoid(b @ Wf) + x, K=128 (2 chunks), N=128 via blockIdx.y
__global__ void __launch_bounds__(256)
final_kernel(const float* __restrict__ x, float* __restrict__ out) {
    uint32_t sb = smem_u32(dsm);
    int tid = threadIdx.x, lane = tid & 31, wid = tid >> 5;
    int p0 = blockIdx.x * 128, cb = blockIdx.y * 64;
    int m0 = (wid & 3) * 32, n0w = (wid >> 2) * 32;
    const __nv_bfloat16* wh = wft_hi + (size_t)cb * 128;
    const __nv_bfloat16* wl = wft_lo + (size_t)cb * 128;
    float acc[2][4][4] = {};

#pragma unroll
    for (int ck = 0; ck < 2; ++ck) {
        stageA_planes(sb, ab_hi[1], ab_lo[1], 128, ck * 64, p0, tid);
        stageB_rows(sb + OF_BH, wh, wl, 128, ck * 64, tid);
        CP_COMMIT();
        CP_WAIT(0);
        __syncthreads();
        mma_chunk32(acc, sb, sb + OF_AL, sb + OF_BH, sb + OF_BL, m0, n0w, lane);
        __syncthreads();
    }

    int r0 = lane >> 2, c0 = (lane & 3) << 1;
#pragma unroll
    for (int mt = 0; mt < 2; ++mt)
#pragma unroll
        for (int nt = 0; nt < 4; ++nt)
#pragma unroll
            for (int h = 0; h < 2; ++h) {
                int p = p0 + m0 + mt * 16 + r0 + h * 8;
                if (p >= NPTS) continue;
                int col = cb + n0w + nt * 8 + c0;
                uint32_t ahv = *(const uint32_t*)(ab_hi[0] + (size_t)p * 128 + col);
                uint32_t alv = *(const uint32_t*)(ab_lo[0] + (size_t)p * 128 + col);
                float a0 = lo2f(ahv) + lo2f(alv), a1 = hi2f(ahv) + hi2f(alv);
                float2 xv = *(const float2*)(x + (size_t)p * 128 + col);
                float g0 = acc[mt][nt][h * 2 + 0], g1 = acc[mt][nt][h * 2 + 1];
                float2 v;
                v.x = a0 * (1.f / (1.f + __expf(-g0))) + xv.x;
                v.y = a1 * (1.f / (1.f + __expf(-g1))) + xv.y;
                *(float2*)(out + (size_t)p * 128 + col) = v;
            }
}

// ---------------------------------------------------------------------------
extern "C" void kernel_launch(void* const* d_in, const int* in_sizes, int n_in,
                              void* d_out, int out_size) {
    const float* x   = (const float*)d_in[0];
    const float* W1s = (const float*)d_in[1];
    const float* Wks = (const float*)d_in[2];
    const float* W2s = (const float*)d_in[3];
    const float* Wf  = (const float*)d_in[4];
    const int*   nbr = (const int*)d_in[5];
    float*       out = (float*)d_out;

    const int SM_CONV = 2 * STG;   // 98304 (double-buffered) -> 2 CTA/SM
    const int SM_FC   = STG;       // 49152

    cudaFuncSetAttribute(conv_fc2_kernel, cudaFuncAttributeMaxDynamicSharedMemorySize, SM_CONV);
    cudaFuncSetAttribute(fc1_kernel,      cudaFuncAttributeMaxDynamicSharedMemorySize, SM_FC);
    cudaFuncSetAttribute(final_kernel,    cudaFuncAttributeMaxDynamicSharedMemorySize, SM_FC);

    prep_w<<<3040, 256>>>(W1s, Wks, W2s, Wf);
    prep_x<<<(NPTS * 128 / 4 + 255) / 256, 256>>>(x);

    dim3 blk256(256), blk512(512);
    dim3 g2(NBLK, 2);

    for (int i = 0; i < 3; ++i) {
        fc1_kernel<<<g2, blk256, SM_FC>>>(i);
        conv_fc2_kernel<<<g2, blk512, SM_CONV>>>(nbr, i);
    }
    final_kernel<<<g2, blk256, SM_FC>>>(x, out);
}

// round 12
// speedup vs baseline: 1.2002x; 1.0102x over previous
#include <cuda_runtime.h>
#include <cuda_bf16.h>
#include <cstdint>
#include <math.h>

#define NPTS 120000
#define NBLK 938   // ceil(120000/128)

// ------------------------- static device scratch ---------------------------
__device__ __nv_bfloat16 xp_hi[(size_t)NPTS * 128], xp_lo[(size_t)NPTS * 128];
__device__ __nv_bfloat16 ab_hi[2][(size_t)NPTS * 128], ab_lo[2][(size_t)NPTS * 128];
__device__ __nv_bfloat16 t_hi[2][(size_t)NPTS * 64],  t_lo[2][(size_t)NPTS * 64];

// preconverted weights, transposed to [n][k], split bf16 hi/lo
__device__ __nv_bfloat16 w1t_hi[49152],  w1t_lo[49152];    // 6 x [64n][128k]
__device__ __nv_bfloat16 wkt_hi[663552], wkt_lo[663552];   // 6 x 27 x [64n][64k]
__device__ __nv_bfloat16 w2t_hi[49152],  w2t_lo[49152];    // 6 x [128n][64k]
__device__ __nv_bfloat16 wft_hi[16384],  wft_lo[16384];    // [128n][128k]

// ------------------------------ helpers ------------------------------------
__device__ __forceinline__ uint32_t smem_u32(const void* p) {
    uint32_t a;
    asm("{ .reg .u64 t; cvta.to.shared.u64 t, %1; cvt.u32.u64 %0, t; }" : "=r"(a) : "l"(p));
    return a;
}
__device__ __forceinline__ uint32_t sw128(uint32_t off) { return off ^ ((off >> 3) & 0x70); }

__device__ __forceinline__ uint32_t packbf(float x, float y) {  // low=bf16(x), high=bf16(y)
    uint32_t r;
    asm("cvt.rn.bf16x2.f32 %0, %1, %2;" : "=r"(r) : "f"(y), "f"(x));
    return r;
}
__device__ __forceinline__ float lo2f(uint32_t p) { return __uint_as_float(p << 16); }
__device__ __forceinline__ float hi2f(uint32_t p) { return __uint_as_float(p & 0xFFFF0000u); }

__device__ __forceinline__ void sts32(uint32_t a, uint32_t v) {
    asm volatile("st.shared.b32 [%0], %1;" :: "r"(a), "r"(v) : "memory");
}
__device__ __forceinline__ void cpasync16(uint32_t dst, const void* src, uint32_t zf) {
    asm volatile("cp.async.cg.shared.global [%0], [%1], 16, %2;"
                 :: "r"(dst), "l"(src), "r"(zf) : "memory");
}
#define CP_COMMIT() asm volatile("cp.async.commit_group;" ::: "memory")
#define CP_WAIT(n)  asm volatile("cp.async.wait_group %0;" :: "n"(n) : "memory")

__device__ __forceinline__ void ldm4(uint32_t r[4], uint32_t addr) {
    asm volatile("ldmatrix.sync.aligned.m8n8.x4.shared.b16 {%0,%1,%2,%3}, [%4];"
                 : "=r"(r[0]), "=r"(r[1]), "=r"(r[2]), "=r"(r[3]) : "r"(addr));
}
__device__ __forceinline__ void mma16816(float d[4], const uint32_t a[4],
                                         uint32_t b0, uint32_t b1) {
    asm volatile("mma.sync.aligned.m16n8k16.row.col.f32.bf16.bf16.f32 "
                 "{%0,%1,%2,%3}, {%4,%5,%6,%7}, {%8,%9}, {%0,%1,%2,%3};"
                 : "+f"(d[0]), "+f"(d[1]), "+f"(d[2]), "+f"(d[3])
                 : "r"(a[0]), "r"(a[1]), "r"(a[2]), "r"(a[3]), "r"(b0), "r"(b1));
}

// ---------------- K=64 chunk MMA, 8-warp variant (m32 x n32 / warp) ---------
__device__ __forceinline__ void mma_chunk32(float acc[2][4][4],
                                            uint32_t Ah, uint32_t Al,
                                            uint32_t Bh, uint32_t Bl,
                                            int m0, int n0w, int lane) {
    const int ar = lane & 15, ak = (lane >> 4) << 3;
    const int bn = (lane & 7) + ((lane & 16) ? 8 : 0), bk = ((lane >> 3) & 1) << 3;
#pragma unroll
    for (int ks = 0; ks < 4; ++ks) {
        uint32_t ah[2][4], al[2][4], bh[2][4], bl[2][4];
#pragma unroll
        for (int mt = 0; mt < 2; ++mt) {
            uint32_t off = sw128((uint32_t)((m0 + mt * 16 + ar) * 128 + (ks * 16 + ak) * 2));
            ldm4(ah[mt], Ah + off);
            ldm4(al[mt], Al + off);
        }
#pragma unroll
        for (int g = 0; g < 2; ++g) {
            uint32_t off = sw128((uint32_t)((n0w + g * 16 + bn) * 128 + (ks * 16 + bk) * 2));
            ldm4(bh[g], Bh + off);
            ldm4(bl[g], Bl + off);
        }
#pragma unroll
        for (int mt = 0; mt < 2; ++mt)
#pragma unroll
            for (int nt = 0; nt < 4; ++nt) {
                int g = nt >> 1, o = (nt & 1) << 1;
                mma16816(acc[mt][nt], ah[mt], bh[g][o], bh[g][o + 1]);
                mma16816(acc[mt][nt], ah[mt], bl[g][o], bl[g][o + 1]);
                mma16816(acc[mt][nt], al[mt], bh[g][o], bh[g][o + 1]);
            }
    }
}

// ---------------- K=64 chunk MMA, 16-warp variant (m32 x n16 / warp) --------
__device__ __forceinline__ void mma_chunk16(float acc[2][2][4],
                                            uint32_t Ah, uint32_t Al,
                                            uint32_t Bh, uint32_t Bl,
                                            int m0, int n0w, int lane) {
    const int ar = lane & 15, ak = (lane >> 4) << 3;
    const int bn = (lane & 7) + ((lane & 16) ? 8 : 0), bk = ((lane >> 3) & 1) << 3;
#pragma unroll
    for (int ks = 0; ks < 4; ++ks) {
        uint32_t ah[2][4], al[2][4], bh[4], bl[4];
#pragma unroll
        for (int mt = 0; mt < 2; ++mt) {
            uint32_t off = sw128((uint32_t)((m0 + mt * 16 + ar) * 128 + (ks * 16 + ak) * 2));
            ldm4(ah[mt], Ah + off);
            ldm4(al[mt], Al + off);
        }
        {
            uint32_t off = sw128((uint32_t)((n0w + bn) * 128 + (ks * 16 + bk) * 2));
            ldm4(bh, Bh + off);
            ldm4(bl, Bl + off);
        }
#pragma unroll
        for (int mt = 0; mt < 2; ++mt)
#pragma unroll
            for (int nt = 0; nt < 2; ++nt) {
                int o = nt << 1;
                mma16816(acc[mt][nt], ah[mt], bh[o], bh[o + 1]);
                mma16816(acc[mt][nt], ah[mt], bl[o], bl[o + 1]);
                mma16816(acc[mt][nt], al[mt], bh[o], bh[o + 1]);
            }
    }
}

// ---- fc2 dual-half MMA: A loaded once per (ks, mt), feeds BOTH N-halves ----
// a2[half][mt][nt][4]; W2 layout at WB: B0h@0, B0l@8K, B1h@16K, B1l@24K.
__device__ __forceinline__ void fc2_mma_dual(float a2[2][2][2][4],
                                             uint32_t Ah, uint32_t Al, uint32_t WB,
                                             int m0, int n0w, int lane) {
    const int ar = lane & 15, ak = (lane >> 4) << 3;
    const int bn = (lane & 7) + ((lane & 16) ? 8 : 0), bk = ((lane >> 3) & 1) << 3;
#pragma unroll
    for (int ks = 0; ks < 4; ++ks) {
        uint32_t boff = sw128((uint32_t)((n0w + bn) * 128 + (ks * 16 + bk) * 2));
        uint32_t b0h[4], b0l[4], b1h[4], b1l[4];
        ldm4(b0h, WB + boff);
        ldm4(b0l, WB + 8192 + boff);
        ldm4(b1h, WB + 16384 + boff);
        ldm4(b1l, WB + 24576 + boff);
#pragma unroll
        for (int mt = 0; mt < 2; ++mt) {
            uint32_t aoff = sw128((uint32_t)((m0 + mt * 16 + ar) * 128 + (ks * 16 + ak) * 2));
            uint32_t ah[4], al[4];
            ldm4(ah, Ah + aoff);
            ldm4(al, Al + aoff);
#pragma unroll
            for (int nt = 0; nt < 2; ++nt) {
                int o = nt << 1;
                mma16816(a2[0][mt][nt], ah, b0h[o], b0h[o + 1]);
                mma16816(a2[0][mt][nt], ah, b0l[o], b0l[o + 1]);
                mma16816(a2[0][mt][nt], al, b0h[o], b0h[o + 1]);
                mma16816(a2[1][mt][nt], ah, b1h[o], b1h[o + 1]);
                mma16816(a2[1][mt][nt], ah, b1l[o], b1l[o + 1]);
                mma16816(a2[1][mt][nt], al, b1h[o], b1h[o + 1]);
            }
        }
    }
}

// --------------------------- staging helpers -------------------------------
// A copy-stage (256 thr): rows p0..p0+127 from [p][ld] planes, cols koff..koff+63
__device__ __forceinline__ void stageA_planes(uint32_t Sa, const __nv_bfloat16* hi,
                                              const __nv_bfloat16* lo, int ld, int koff,
                                              int p0, int tid) {
    int row = tid >> 1, plane = tid & 1, p = p0 + row;
    const __nv_bfloat16* src = (plane ? lo : hi) + (size_t)(p < NPTS ? p : 0) * ld + koff;
    uint32_t zf = (p < NPTS) ? 16u : 0u;
    uint32_t base = Sa + (plane << 14);
#pragma unroll
    for (int j = 0; j < 8; ++j)
        cpasync16(base + sw128((uint32_t)(row * 128 + j * 16)), src + j * 8, zf);
}

// A gather-stage (512 thr): rows via nbr[:,kk], 64-col planes
__device__ __forceinline__ void stageA_gather512(uint32_t Sa, const __nv_bfloat16* hi,
                                                 const __nv_bfloat16* lo,
                                                 const int* __restrict__ nbr,
                                                 int p0, int kk, int tid) {
#pragma unroll
    for (int i = 0; i < 4; ++i) {
        int idx = tid + (i << 9);            // 0..2047
        int plane = idx >> 10, r10 = idx & 1023, row = r10 >> 3, j = r10 & 7;
        int p = p0 + row;
        int nb = (p < NPTS) ? __ldg(&nbr[(size_t)p * 27 + kk]) : -1;
        const __nv_bfloat16* src = (plane ? lo : hi) + (size_t)(nb < 0 ? 0 : nb) * 64 + j * 8;
        cpasync16(Sa + (plane << 14) + sw128((uint32_t)(row * 128 + j * 16)),
                  src, (nb >= 0) ? 16u : 0u);
    }
}

// B copy-stage, 256 thr: 64 rows x 64k from [n][srcld] planes at column koff
__device__ __forceinline__ void stageB_rows(uint32_t Sb, const __nv_bfloat16* hi,
                                            const __nv_bfloat16* lo, int srcld,
                                            int koff, int tid) {
#pragma unroll
    for (int j = 0; j < 4; ++j) {
        int fl = tid + (j << 8);
        int plane = fl >> 9, r9 = fl & 511, n = r9 >> 3, jj = r9 & 7;
        const __nv_bfloat16* src = (plane ? lo : hi) + (size_t)n * srcld + koff + jj * 8;
        cpasync16(Sb + (plane << 13) + sw128((uint32_t)(n * 128 + jj * 16)), src, 16u);
    }
}
// B copy-stage, 512 thr (srcld = 64)
__device__ __forceinline__ void stageB_rows512(uint32_t Sb, const __nv_bfloat16* hi,
                                               const __nv_bfloat16* lo, int tid) {
#pragma unroll
    for (int j = 0; j < 2; ++j) {
        int fl = tid + (j << 9);
        int plane = fl >> 9, r9 = fl & 511, n = r9 >> 3, jj = r9 & 7;
        const __nv_bfloat16* src = (plane ? lo : hi) + (size_t)n * 64 + jj * 8;
        cpasync16(Sb + (plane << 13) + sw128((uint32_t)(n * 128 + jj * 16)), src, 16u);
    }
}

// relu + split epilogue into [p][ld] planes (8-warp m32n32 variant)
__device__ __forceinline__ void epi_planes32(const float acc[2][4][4],
                                             __nv_bfloat16* ghi, __nv_bfloat16* glo,
                                             int ld, int colbase,
                                             int p0, int m0, int n0w, int lane) {
    int r0 = lane >> 2, c0 = (lane & 3) << 1;
#pragma unroll
    for (int mt = 0; mt < 2; ++mt)
#pragma unroll
        for (int nt = 0; nt < 4; ++nt)
#pragma unroll
            for (int h = 0; h < 2; ++h) {
                int p = p0 + m0 + mt * 16 + r0 + h * 8;
                if (p >= NPTS) continue;
                int col = colbase + n0w + nt * 8 + c0;
                float v0 = fmaxf(acc[mt][nt][h * 2 + 0], 0.f);
                float v1 = fmaxf(acc[mt][nt][h * 2 + 1], 0.f);
                uint32_t hv = packbf(v0, v1);
                uint32_t lv = packbf(v0 - lo2f(hv), v1 - hi2f(hv));
                *(uint32_t*)(ghi + (size_t)p * ld + col) = hv;
                *(uint32_t*)(glo + (size_t)p * ld + col) = lv;
            }
}

extern __shared__ char dsm[];
// stage layout (49152 B): Ah +0 (16K), Al +16K, Bh +32K (8K), Bl +40K (8K)
#define STG   49152
#define OF_AL 16384
#define OF_BH 32768
#define OF_BL 40960

// ------------------------- weight prep (once per graph) --------------------
__global__ void prep_w(const float* __restrict__ W1s, const float* __restrict__ Wks,
                       const float* __restrict__ W2s, const float* __restrict__ Wf) {
    int idx = blockIdx.x * 256 + threadIdx.x;
    float w;
    __nv_bfloat16 *dh, *dl;
    size_t d;
    if (idx < 49152) {
        int i = idx / 8192, r = idx % 8192, n = r / 128, k = r % 128;
        w = W1s[(size_t)i * 8192 + (size_t)k * 64 + n];
        dh = w1t_hi; dl = w1t_lo; d = (size_t)i * 8192 + n * 128 + k;
    } else if (idx < 712704) {
        int t = idx - 49152;
        int j = t / 4096, r = t % 4096, n = r / 64, k = r % 64;
        w = Wks[(size_t)j * 4096 + (size_t)k * 64 + n];
        dh = wkt_hi; dl = wkt_lo; d = (size_t)j * 4096 + n * 64 + k;
    } else if (idx < 761856) {
        int t = idx - 712704;
        int i = t / 8192, r = t % 8192, n = r / 64, k = r % 64;
        w = W2s[(size_t)i * 8192 + (size_t)k * 128 + n];
        dh = w2t_hi; dl = w2t_lo; d = (size_t)i * 8192 + n * 64 + k;
    } else if (idx < 778240) {
        int t = idx - 761856;
        int n = t / 128, k = t % 128;
        w = Wf[(size_t)k * 128 + n];
        dh = wft_hi; dl = wft_lo; d = (size_t)n * 128 + k;
    } else return;
    __nv_bfloat16 h = __float2bfloat16(w);
    dh[d] = h;
    dl[d] = __float2bfloat16(w - __bfloat162float(h));
}

// x -> split planes (once per graph)
__global__ void prep_x(const float* __restrict__ x) {
    size_t i4 = (size_t)blockIdx.x * 256 + threadIdx.x;
    if (i4 >= (size_t)NPTS * 128 / 4) return;
    float4 v = ((const float4*)x)[i4];
    uint32_t h01 = packbf(v.x, v.y), h23 = packbf(v.z, v.w);
    uint32_t l01 = packbf(v.x - lo2f(h01), v.y - hi2f(h01));
    uint32_t l23 = packbf(v.z - lo2f(h23), v.w - hi2f(h23));
    ((uint32_t*)xp_hi)[i4 * 2] = h01; ((uint32_t*)xp_hi)[i4 * 2 + 1] = h23;
    ((uint32_t*)xp_lo)[i4 * 2] = l01; ((uint32_t*)xp_lo)[i4 * 2 + 1] = l23;
}

// ----------------------- conv + fused fc2 -----------------------------------
// Mainloop (512 thr, 16 warps m32xn16): u = relu(conv3(t[branch])), regs in acc.
// W2 prefetched into buffer 1 during the LAST tap. Epilogue: u -> smem planes,
// dual-half fc2 MMA (A loaded once), residual + relu + split -> ab[branch].
__global__ void __launch_bounds__(512, 2)
conv_fc2_kernel(const int* __restrict__ nbr, int unit) {
    uint32_t sb = smem_u32(dsm);
    int tid = threadIdx.x, lane = tid & 31, wid = tid >> 5;
    int p0 = blockIdx.x * 128;
    int branch = blockIdx.y;
    int layer = unit + 3 * branch;
    int m0 = (wid & 3) * 32, n0w = (wid >> 2) * 16;
    const __nv_bfloat16* th = t_hi[branch];
    const __nv_bfloat16* tl = t_lo[branch];
    const __nv_bfloat16* wh = wkt_hi + (size_t)layer * 27 * 4096;
    const __nv_bfloat16* wl = wkt_lo + (size_t)layer * 27 * 4096;
    const __nv_bfloat16* w2h = w2t_hi + (size_t)layer * 8192;   // [128n][64k]
    const __nv_bfloat16* w2l = w2t_lo + (size_t)layer * 8192;
    const uint32_t WB = sb + STG;   // W2 region inside buffer 1
    float acc[2][2][4] = {};

    stageA_gather512(sb, th, tl, nbr, p0, 0, tid);
    stageB_rows512(sb + OF_BH, wh, wl, tid);
    CP_COMMIT();

    for (int kk = 0; kk < 27; ++kk) {
        uint32_t S = sb + (uint32_t)(kk & 1) * STG;
        if (kk < 26) {
            uint32_t S2 = sb + (uint32_t)((kk + 1) & 1) * STG;
            stageA_gather512(S2, th, tl, nbr, p0, kk + 1, tid);
            stageB_rows512(S2 + OF_BH, wh + (size_t)(kk + 1) * 4096,
                           wl + (size_t)(kk + 1) * 4096, tid);
            CP_COMMIT();
            CP_WAIT(1);
        } else {
            // last tap: prefetch W2 halves into buffer 1 (idle), overlap with MMA
            stageB_rows512(WB,         w2h,        w2l,        tid);
            stageB_rows512(WB + 16384, w2h + 4096, w2l + 4096, tid);
            CP_COMMIT();
            CP_WAIT(1);   // tap-26 data ready; W2 still in flight
        }
        __syncthreads();
        mma_chunk16(acc, S, S + OF_AL, S + OF_BH, S + OF_BL, m0, n0w, lane);
        __syncthreads();
    }

    // ---- write u tile (relu + split) into smem planes at buffer 0 ----
    int r0 = lane >> 2, c0 = (lane & 3) << 1;
#pragma unroll
    for (int mt = 0; mt < 2; ++mt)
#pragma unroll
        for (int nt = 0; nt < 2; ++nt)
#pragma unroll
            for (int h = 0; h < 2; ++h) {
                int row = m0 + mt * 16 + r0 + h * 8;
                int col = n0w + nt * 8 + c0;
                float v0 = fmaxf(acc[mt][nt][h * 2 + 0], 0.f);
                float v1 = fmaxf(acc[mt][nt][h * 2 + 1], 0.f);
                uint32_t hv = packbf(v0, v1);
                uint32_t lv = packbf(v0 - lo2f(hv), v1 - hi2f(hv));
                uint32_t off = sw128((uint32_t)(row * 128 + col * 2));
                sts32(sb + off, hv);
                sts32(sb + OF_AL + off, lv);
            }

    CP_WAIT(0);        // W2 arrived
    __syncthreads();   // u planes + W2 visible

    // ---- fc2: dual-half MMA over the smem u tile ----
    const __nv_bfloat16* rh = (unit == 0) ? xp_hi : ab_hi[branch];
    const __nv_bfloat16* rl = (unit == 0) ? xp_lo : ab_lo[branch];
    __nv_bfloat16* oh = ab_hi[branch];
    __nv_bfloat16* ol = ab_lo[branch];

    float a2[2][2][2][4] = {};
    fc2_mma_dual(a2, sb, sb + OF_AL, WB, m0, n0w, lane);

#pragma unroll
    for (int half = 0; half < 2; ++half) {
        int cb = half * 64;
#pragma unroll
        for (int mt = 0; mt < 2; ++mt)
#pragma unroll
            for (int nt = 0; nt < 2; ++nt)
#pragma unroll
                for (int h = 0; h < 2; ++h) {
                    int p = p0 + m0 + mt * 16 + r0 + h * 8;
                    if (p >= NPTS) continue;
                    int col = cb + n0w + nt * 8 + c0;
                    uint32_t rhv = *(const uint32_t*)(rh + (size_t)p * 128 + col);
                    uint32_t rlv = *(const uint32_t*)(rl + (size_t)p * 128 + col);
                    float v0 = fmaxf(a2[half][mt][nt][h * 2 + 0] + lo2f(rhv) + lo2f(rlv), 0.f);
                    float v1 = fmaxf(a2[half][mt][nt][h * 2 + 1] + hi2f(rhv) + hi2f(rlv), 0.f);
                    uint32_t hv = packbf(v0, v1);
                    uint32_t lv = packbf(v0 - lo2f(hv), v1 - hi2f(hv));
                    *(uint32_t*)(oh + (size_t)p * 128 + col) = hv;
                    *(uint32_t*)(ol + (size_t)p * 128 + col) = lv;
                }
    }
}

// ------------------------------ fc1 ----------------------------------------
// t[branch] = relu( src @ W1[layer] ), K=128, both chunks prefetched (96KB).
__global__ void __launch_bounds__(256)
fc1_kernel(int unit) {
    uint32_t sb = smem_u32(dsm);
    int tid = threadIdx.x, lane = tid & 31, wid = tid >> 5;
    int p0 = blockIdx.x * 128;
    int branch = blockIdx.y;
    int layer = unit + 3 * branch;
    int m0 = (wid & 3) * 32, n0w = (wid >> 2) * 32;
    const __nv_bfloat16* sh = (unit == 0) ? xp_hi : ab_hi[branch];
    const __nv_bfloat16* sl = (unit == 0) ? xp_lo : ab_lo[branch];
    const __nv_bfloat16* wh = w1t_hi + (size_t)layer * 8192;
    const __nv_bfloat16* wl = w1t_lo + (size_t)layer * 8192;
    float acc[2][4][4] = {};

    // prefetch both K-chunks
    stageA_planes(sb, sh, sl, 128, 0, p0, tid);
    stageB_rows(sb + OF_BH, wh, wl, 128, 0, tid);
    CP_COMMIT();
    stageA_planes(sb + STG, sh, sl, 128, 64, p0, tid);
    stageB_rows(sb + STG + OF_BH, wh, wl, 128, 64, tid);
    CP_COMMIT();

    CP_WAIT(1);
    __syncthreads();
    mma_chunk32(acc, sb, sb + OF_AL, sb + OF_BH, sb + OF_BL, m0, n0w, lane);
    CP_WAIT(0);
    __syncthreads();
    {
        uint32_t S = sb + STG;
        mma_chunk32(acc, S, S + OF_AL, S + OF_BH, S + OF_BL, m0, n0w, lane);
    }
    epi_planes32(acc, t_hi[branch], t_lo[branch], 64, 0, p0, m0, n0w, lane);
}

// ------------------------------ final --------------------------------------
// out = a * sigmoid(b @ Wf) + x, K=128 both chunks prefetched, N via blockIdx.y
__global__ void __launch_bounds__(256)
final_kernel(const float* __restrict__ x, float* __restrict__ out) {
    uint32_t sb = smem_u32(dsm);
    int tid = threadIdx.x, lane = tid & 31, wid = tid >> 5;
    int p0 = blockIdx.x * 128, cb = blockIdx.y * 64;
    int m0 = (wid & 3) * 32, n0w = (wid >> 2) * 32;
    const __nv_bfloat16* wh = wft_hi + (size_t)cb * 128;
    const __nv_bfloat16* wl = wft_lo + (size_t)cb * 128;
    float acc[2][4][4] = {};

    stageA_planes(sb, ab_hi[1], ab_lo[1], 128, 0, p0, tid);
    stageB_rows(sb + OF_BH, wh, wl, 128, 0, tid);
    CP_COMMIT();
    stageA_planes(sb + STG, ab_hi[1], ab_lo[1], 128, 64, p0, tid);
    stageB_rows(sb + STG + OF_BH, wh, wl, 128, 64, tid);
    CP_COMMIT();

    CP_WAIT(1);
    __syncthreads();
    mma_chunk32(acc, sb, sb + OF_AL, sb + OF_BH, sb + OF_BL, m0, n0w, lane);
    CP_WAIT(0);
    __syncthreads();
    {
        uint32_t S = sb + STG;
        mma_chunk32(acc, S, S + OF_AL, S + OF_BH, S + OF_BL, m0, n0w, lane);
    }

    int r0 = lane >> 2, c0 = (lane & 3) << 1;
#pragma unroll
    for (int mt = 0; mt < 2; ++mt)
#pragma unroll
        for (int nt = 0; nt < 4; ++nt)
#pragma unroll
            for (int h = 0; h < 2; ++h) {
                int p = p0 + m0 + mt * 16 + r0 + h * 8;
                if (p >= NPTS) continue;
                int col = cb + n0w + nt * 8 + c0;
                uint32_t ahv = *(const uint32_t*)(ab_hi[0] + (size_t)p * 128 + col);
                uint32_t alv = *(const uint32_t*)(ab_lo[0] + (size_t)p * 128 + col);
                float a0 = lo2f(ahv) + lo2f(alv), a1 = hi2f(ahv) + hi2f(alv);
                float2 xv = *(const float2*)(x + (size_t)p * 128 + col);
                float g0 = acc[mt][nt][h * 2 + 0], g1 = acc[mt][nt][h * 2 + 1];
                float2 v;
                v.x = a0 * (1.f / (1.f + __expf(-g0))) + xv.x;
                v.y = a1 * (1.f / (1.f + __expf(-g1))) + xv.y;
                *(float2*)(out + (size_t)p * 128 + col) = v;
            }
}

// ---------------------------------------------------------------------------
extern "C" void kernel_launch(void* const* d_in, const int* in_sizes, int n_in,
                              void* d_out, int out_size) {
    const float* x   = (const float*)d_in[0];
    const float* W1s = (const float*)d_in[1];
    const float* Wks = (const float*)d_in[2];
    const float* W2s = (const float*)d_in[3];
    const float* Wf  = (const float*)d_in[4];
    const int*   nbr = (const int*)d_in[5];
    float*       out = (float*)d_out;

    const int SM_CONV = 2 * STG;   // 98304 -> 2 CTA/SM
    const int SM_FC   = 2 * STG;   // 98304 (double-buffered chunks) -> 2 CTA/SM

    cudaFuncSetAttribute(conv_fc2_kernel, cudaFuncAttributeMaxDynamicSharedMemorySize, SM_CONV);
    cudaFuncSetAttribute(fc1_kernel,      cudaFuncAttributeMaxDynamicSharedMemorySize, SM_FC);
    cudaFuncSetAttribute(final_kernel,    cudaFuncAttributeMaxDynamicSharedMemorySize, SM_FC);

    prep_w<<<3040, 256>>>(W1s, Wks, W2s, Wf);
    prep_x<<<(NPTS * 128 / 4 + 255) / 256, 256>>>(x);

    dim3 blk256(256), blk512(512);
    dim3 g2(NBLK, 2);

    for (int i = 0; i < 3; ++i) {
        fc1_kernel<<<g2, blk256, SM_FC>>>(i);
        conv_fc2_kernel<<<g2, blk512, SM_CONV>>>(nbr, i);
    }
    final_kernel<<<g2, blk256, SM_FC>>>(x, out);
}

// round 13
// speedup vs baseline: 1.2429x; 1.0356x over previous
#include <cuda_runtime.h>
#include <cuda_bf16.h>
#include <cstdint>
#include <math.h>

#define NPTS 120000
#define NBLK 938   // ceil(120000/128)

// ------------------------- static device scratch ---------------------------
__device__ __nv_bfloat16 xp_hi[(size_t)NPTS * 128], xp_lo[(size_t)NPTS * 128];
__device__ __nv_bfloat16 ab_hi[2][(size_t)NPTS * 128], ab_lo[2][(size_t)NPTS * 128];
__device__ __nv_bfloat16 t_hi[2][(size_t)NPTS * 64],  t_lo[2][(size_t)NPTS * 64];

// preconverted weights, transposed to [n][k], split bf16 hi/lo
__device__ __nv_bfloat16 w1t_hi[49152],  w1t_lo[49152];    // 6 x [64n][128k]
__device__ __nv_bfloat16 wkt_hi[663552], wkt_lo[663552];   // 6 x 27 x [64n][64k]
__device__ __nv_bfloat16 w2t_hi[49152],  w2t_lo[49152];    // 6 x [128n][64k]
__device__ __nv_bfloat16 wft_hi[16384],  wft_lo[16384];    // [128n][128k]

// ------------------------------ helpers ------------------------------------
__device__ __forceinline__ uint32_t smem_u32(const void* p) {
    uint32_t a;
    asm("{ .reg .u64 t; cvta.to.shared.u64 t, %1; cvt.u32.u64 %0, t; }" : "=r"(a) : "l"(p));
    return a;
}
__device__ __forceinline__ uint32_t sw128(uint32_t off) { return off ^ ((off >> 3) & 0x70); }

__device__ __forceinline__ uint32_t packbf(float x, float y) {  // low=bf16(x), high=bf16(y)
    uint32_t r;
    asm("cvt.rn.bf16x2.f32 %0, %1, %2;" : "=r"(r) : "f"(y), "f"(x));
    return r;
}
__device__ __forceinline__ float lo2f(uint32_t p) { return __uint_as_float(p << 16); }
__device__ __forceinline__ float hi2f(uint32_t p) { return __uint_as_float(p & 0xFFFF0000u); }

__device__ __forceinline__ void sts32(uint32_t a, uint32_t v) {
    asm volatile("st.shared.b32 [%0], %1;" :: "r"(a), "r"(v) : "memory");
}
__device__ __forceinline__ void cpasync16(uint32_t dst, const void* src, uint32_t zf) {
    asm volatile("cp.async.cg.shared.global [%0], [%1], 16, %2;"
                 :: "r"(dst), "l"(src), "r"(zf) : "memory");
}
#define CP_COMMIT() asm volatile("cp.async.commit_group;" ::: "memory")
#define CP_WAIT(n)  asm volatile("cp.async.wait_group %0;" :: "n"(n) : "memory")

__device__ __forceinline__ void ldm4(uint32_t r[4], uint32_t addr) {
    asm volatile("ldmatrix.sync.aligned.m8n8.x4.shared.b16 {%0,%1,%2,%3}, [%4];"
                 : "=r"(r[0]), "=r"(r[1]), "=r"(r[2]), "=r"(r[3]) : "r"(addr));
}
__device__ __forceinline__ void mma16816(float d[4], const uint32_t a[4],
                                         uint32_t b0, uint32_t b1) {
    asm volatile("mma.sync.aligned.m16n8k16.row.col.f32.bf16.bf16.f32 "
                 "{%0,%1,%2,%3}, {%4,%5,%6,%7}, {%8,%9}, {%0,%1,%2,%3};"
                 : "+f"(d[0]), "+f"(d[1]), "+f"(d[2]), "+f"(d[3])
                 : "r"(a[0]), "r"(a[1]), "r"(a[2]), "r"(a[3]), "r"(b0), "r"(b1));
}

// ---------------- K=64 chunk MMA, 16-warp variant (m32 x n16 / warp) --------
__device__ __forceinline__ void mma_chunk16(float acc[2][2][4],
                                            uint32_t Ah, uint32_t Al,
                                            uint32_t Bh, uint32_t Bl,
                                            int m0, int n0w, int lane) {
    const int ar = lane & 15, ak = (lane >> 4) << 3;
    const int bn = (lane & 7) + ((lane & 16) ? 8 : 0), bk = ((lane >> 3) & 1) << 3;
#pragma unroll
    for (int ks = 0; ks < 4; ++ks) {
        uint32_t ah[2][4], al[2][4], bh[4], bl[4];
#pragma unroll
        for (int mt = 0; mt < 2; ++mt) {
            uint32_t off = sw128((uint32_t)((m0 + mt * 16 + ar) * 128 + (ks * 16 + ak) * 2));
            ldm4(ah[mt], Ah + off);
            ldm4(al[mt], Al + off);
        }
        {
            uint32_t off = sw128((uint32_t)((n0w + bn) * 128 + (ks * 16 + bk) * 2));
            ldm4(bh, Bh + off);
            ldm4(bl, Bl + off);
        }
#pragma unroll
        for (int mt = 0; mt < 2; ++mt)
#pragma unroll
            for (int nt = 0; nt < 2; ++nt) {
                int o = nt << 1;
                mma16816(acc[mt][nt], ah[mt], bh[o], bh[o + 1]);
                mma16816(acc[mt][nt], ah[mt], bl[o], bl[o + 1]);
                mma16816(acc[mt][nt], al[mt], bh[o], bh[o + 1]);
            }
    }
}

// ---- fc2 dual-half MMA: A loaded once per (ks, mt), feeds BOTH N-halves ----
__device__ __forceinline__ void fc2_mma_dual(float a2[2][2][2][4],
                                             uint32_t Ah, uint32_t Al, uint32_t WB,
                                             int m0, int n0w, int lane) {
    const int ar = lane & 15, ak = (lane >> 4) << 3;
    const int bn = (lane & 7) + ((lane & 16) ? 8 : 0), bk = ((lane >> 3) & 1) << 3;
#pragma unroll
    for (int ks = 0; ks < 4; ++ks) {
        uint32_t boff = sw128((uint32_t)((n0w + bn) * 128 + (ks * 16 + bk) * 2));
        uint32_t b0h[4], b0l[4], b1h[4], b1l[4];
        ldm4(b0h, WB + boff);
        ldm4(b0l, WB + 8192 + boff);
        ldm4(b1h, WB + 16384 + boff);
        ldm4(b1l, WB + 24576 + boff);
#pragma unroll
        for (int mt = 0; mt < 2; ++mt) {
            uint32_t aoff = sw128((uint32_t)((m0 + mt * 16 + ar) * 128 + (ks * 16 + ak) * 2));
            uint32_t ah[4], al[4];
            ldm4(ah, Ah + aoff);
            ldm4(al, Al + aoff);
#pragma unroll
            for (int nt = 0; nt < 2; ++nt) {
                int o = nt << 1;
                mma16816(a2[0][mt][nt], ah, b0h[o], b0h[o + 1]);
                mma16816(a2[0][mt][nt], ah, b0l[o], b0l[o + 1]);
                mma16816(a2[0][mt][nt], al, b0h[o], b0h[o + 1]);
                mma16816(a2[1][mt][nt], ah, b1h[o], b1h[o + 1]);
                mma16816(a2[1][mt][nt], ah, b1l[o], b1l[o + 1]);
                mma16816(a2[1][mt][nt], al, b1h[o], b1h[o + 1]);
            }
        }
    }
}

// --------------------------- staging (512 threads) --------------------------
// A copy-stage: 128 rows x 64 cols from [p][ld] planes at koff, plane pitch 16KB
__device__ __forceinline__ void stageA_planes512(uint32_t Sa, const __nv_bfloat16* hi,
                                                 const __nv_bfloat16* lo, int ld, int koff,
                                                 int p0, int tid) {
#pragma unroll
    for (int i = 0; i < 4; ++i) {
        int idx = tid + (i << 9);            // 0..2047
        int plane = idx >> 10, r10 = idx & 1023, row = r10 >> 3, j = r10 & 7;
        int p = p0 + row;
        const __nv_bfloat16* src = (plane ? lo : hi) + (size_t)(p < NPTS ? p : 0) * ld + koff + j * 8;
        cpasync16(Sa + (plane << 14) + sw128((uint32_t)(row * 128 + j * 16)),
                  src, (p < NPTS) ? 16u : 0u);
    }
}

// A gather-stage: 128 rows via nbr[:,kk], 64-col planes
__device__ __forceinline__ void stageA_gather512(uint32_t Sa, const __nv_bfloat16* hi,
                                                 const __nv_bfloat16* lo,
                                                 const int* __restrict__ nbr,
                                                 int p0, int kk, int tid) {
#pragma unroll
    for (int i = 0; i < 4; ++i) {
        int idx = tid + (i << 9);            // 0..2047
        int plane = idx >> 10, r10 = idx & 1023, row = r10 >> 3, j = r10 & 7;
        int p = p0 + row;
        int nb = (p < NPTS) ? __ldg(&nbr[(size_t)p * 27 + kk]) : -1;
        const __nv_bfloat16* src = (plane ? lo : hi) + (size_t)(nb < 0 ? 0 : nb) * 64 + j * 8;
        cpasync16(Sa + (plane << 14) + sw128((uint32_t)(row * 128 + j * 16)),
                  src, (nb >= 0) ? 16u : 0u);
    }
}

// B copy-stage: 64 rows x 64k from [n][srcld] planes at koff, plane pitch 8KB
__device__ __forceinline__ void stageB512(uint32_t Sb, const __nv_bfloat16* hi,
                                          const __nv_bfloat16* lo, int srcld,
                                          int koff, int tid) {
#pragma unroll
    for (int j = 0; j < 2; ++j) {
        int fl = tid + (j << 9);
        int plane = fl >> 9, r9 = fl & 511, n = r9 >> 3, jj = r9 & 7;
        const __nv_bfloat16* src = (plane ? lo : hi) + (size_t)n * srcld + koff + jj * 8;
        cpasync16(Sb + (plane << 13) + sw128((uint32_t)(n * 128 + jj * 16)), src, 16u);
    }
}

// relu + split epilogue into [p][ld] planes (m32 x n16 acc)
__device__ __forceinline__ void epi_planes16(const float acc[2][2][4],
                                             __nv_bfloat16* ghi, __nv_bfloat16* glo,
                                             int ld, int colbase,
                                             int p0, int m0, int n0w, int lane) {
    int r0 = lane >> 2, c0 = (lane & 3) << 1;
#pragma unroll
    for (int mt = 0; mt < 2; ++mt)
#pragma unroll
        for (int nt = 0; nt < 2; ++nt)
#pragma unroll
            for (int h = 0; h < 2; ++h) {
                int p = p0 + m0 + mt * 16 + r0 + h * 8;
                if (p >= NPTS) continue;
                int col = colbase + n0w + nt * 8 + c0;
                float v0 = fmaxf(acc[mt][nt][h * 2 + 0], 0.f);
                float v1 = fmaxf(acc[mt][nt][h * 2 + 1], 0.f);
                uint32_t hv = packbf(v0, v1);
                uint32_t lv = packbf(v0 - lo2f(hv), v1 - hi2f(hv));
                *(uint32_t*)(ghi + (size_t)p * ld + col) = hv;
                *(uint32_t*)(glo + (size_t)p * ld + col) = lv;
            }
}

extern __shared__ char dsm[];
// stage layout (49152 B): Ah +0 (16K), Al +16K, Bh +32K (8K), Bl +40K (8K)
#define STG   49152
#define OF_AL 16384
#define OF_BH 32768
#define OF_BL 40960

// ------------------------- weight prep (once per graph) --------------------
__global__ void prep_w(const float* __restrict__ W1s, const float* __restrict__ Wks,
                       const float* __restrict__ W2s, const float* __restrict__ Wf) {
    int idx = blockIdx.x * 256 + threadIdx.x;
    float w;
    __nv_bfloat16 *dh, *dl;
    size_t d;
    if (idx < 49152) {
        int i = idx / 8192, r = idx % 8192, n = r / 128, k = r % 128;
        w = W1s[(size_t)i * 8192 + (size_t)k * 64 + n];
        dh = w1t_hi; dl = w1t_lo; d = (size_t)i * 8192 + n * 128 + k;
    } else if (idx < 712704) {
        int t = idx - 49152;
        int j = t / 4096, r = t % 4096, n = r / 64, k = r % 64;
        w = Wks[(size_t)j * 4096 + (size_t)k * 64 + n];
        dh = wkt_hi; dl = wkt_lo; d = (size_t)j * 4096 + n * 64 + k;
    } else if (idx < 761856) {
        int t = idx - 712704;
        int i = t / 8192, r = t % 8192, n = r / 64, k = r % 64;
        w = W2s[(size_t)i * 8192 + (size_t)k * 128 + n];
        dh = w2t_hi; dl = w2t_lo; d = (size_t)i * 8192 + n * 64 + k;
    } else if (idx < 778240) {
        int t = idx - 761856;
        int n = t / 128, k = t % 128;
        w = Wf[(size_t)k * 128 + n];
        dh = wft_hi; dl = wft_lo; d = (size_t)n * 128 + k;
    } else return;
    __nv_bfloat16 h = __float2bfloat16(w);
    dh[d] = h;
    dl[d] = __float2bfloat16(w - __bfloat162float(h));
}

// x -> split planes (once per graph)
__global__ void prep_x(const float* __restrict__ x) {
    size_t i4 = (size_t)blockIdx.x * 256 + threadIdx.x;
    if (i4 >= (size_t)NPTS * 128 / 4) return;
    float4 v = ((const float4*)x)[i4];
    uint32_t h01 = packbf(v.x, v.y), h23 = packbf(v.z, v.w);
    uint32_t l01 = packbf(v.x - lo2f(h01), v.y - hi2f(h01));
    uint32_t l23 = packbf(v.z - lo2f(h23), v.w - hi2f(h23));
    ((uint32_t*)xp_hi)[i4 * 2] = h01; ((uint32_t*)xp_hi)[i4 * 2 + 1] = h23;
    ((uint32_t*)xp_lo)[i4 * 2] = l01; ((uint32_t*)xp_lo)[i4 * 2 + 1] = l23;
}

// ----------------------- conv + fused fc2 -----------------------------------
__global__ void __launch_bounds__(512, 2)
conv_fc2_kernel(const int* __restrict__ nbr, int unit) {
    uint32_t sb = smem_u32(dsm);
    int tid = threadIdx.x, lane = tid & 31, wid = tid >> 5;
    int p0 = blockIdx.x * 128;
    int branch = blockIdx.y;
    int layer = unit + 3 * branch;
    int m0 = (wid & 3) * 32, n0w = (wid >> 2) * 16;
    const __nv_bfloat16* th = t_hi[branch];
    const __nv_bfloat16* tl = t_lo[branch];
    const __nv_bfloat16* wh = wkt_hi + (size_t)layer * 27 * 4096;
    const __nv_bfloat16* wl = wkt_lo + (size_t)layer * 27 * 4096;
    const __nv_bfloat16* w2h = w2t_hi + (size_t)layer * 8192;   // [128n][64k]
    const __nv_bfloat16* w2l = w2t_lo + (size_t)layer * 8192;
    const uint32_t WB = sb + STG;   // W2 region inside buffer 1
    float acc[2][2][4] = {};

    stageA_gather512(sb, th, tl, nbr, p0, 0, tid);
    stageB512(sb + OF_BH, wh, wl, 64, 0, tid);
    CP_COMMIT();

    for (int kk = 0; kk < 27; ++kk) {
        uint32_t S = sb + (uint32_t)(kk & 1) * STG;
        if (kk < 26) {
            uint32_t S2 = sb + (uint32_t)((kk + 1) & 1) * STG;
            stageA_gather512(S2, th, tl, nbr, p0, kk + 1, tid);
            stageB512(S2 + OF_BH, wh + (size_t)(kk + 1) * 4096,
                      wl + (size_t)(kk + 1) * 4096, 64, 0, tid);
            CP_COMMIT();
            CP_WAIT(1);
        } else {
            // last tap: prefetch W2 halves into buffer 1 (idle), overlap with MMA
            stageB512(WB,         w2h,        w2l,        64, 0, tid);
            stageB512(WB + 16384, w2h + 4096, w2l + 4096, 64, 0, tid);
            CP_COMMIT();
            CP_WAIT(1);
        }
        __syncthreads();
        mma_chunk16(acc, S, S + OF_AL, S + OF_BH, S + OF_BL, m0, n0w, lane);
        __syncthreads();
    }

    // ---- write u tile (relu + split) into smem planes at buffer 0 ----
    int r0 = lane >> 2, c0 = (lane & 3) << 1;
#pragma unroll
    for (int mt = 0; mt < 2; ++mt)
#pragma unroll
        for (int nt = 0; nt < 2; ++nt)
#pragma unroll
            for (int h = 0; h < 2; ++h) {
                int row = m0 + mt * 16 + r0 + h * 8;
                int col = n0w + nt * 8 + c0;
                float v0 = fmaxf(acc[mt][nt][h * 2 + 0], 0.f);
                float v1 = fmaxf(acc[mt][nt][h * 2 + 1], 0.f);
                uint32_t hv = packbf(v0, v1);
                uint32_t lv = packbf(v0 - lo2f(hv), v1 - hi2f(hv));
                uint32_t off = sw128((uint32_t)(row * 128 + col * 2));
                sts32(sb + off, hv);
                sts32(sb + OF_AL + off, lv);
            }

    CP_WAIT(0);
    __syncthreads();

    // ---- fc2: dual-half MMA over the smem u tile ----
    const __nv_bfloat16* rh = (unit == 0) ? xp_hi : ab_hi[branch];
    const __nv_bfloat16* rl = (unit == 0) ? xp_lo : ab_lo[branch];
    __nv_bfloat16* oh = ab_hi[branch];
    __nv_bfloat16* ol = ab_lo[branch];

    float a2[2][2][2][4] = {};
    fc2_mma_dual(a2, sb, sb + OF_AL, WB, m0, n0w, lane);

#pragma unroll
    for (int half = 0; half < 2; ++half) {
        int cb = half * 64;
#pragma unroll
        for (int mt = 0; mt < 2; ++mt)
#pragma unroll
            for (int nt = 0; nt < 2; ++nt)
#pragma unroll
                for (int h = 0; h < 2; ++h) {
                    int p = p0 + m0 + mt * 16 + r0 + h * 8;
                    if (p >= NPTS) continue;
                    int col = cb + n0w + nt * 8 + c0;
                    uint32_t rhv = *(const uint32_t*)(rh + (size_t)p * 128 + col);
                    uint32_t rlv = *(const uint32_t*)(rl + (size_t)p * 128 + col);
                    float v0 = fmaxf(a2[half][mt][nt][h * 2 + 0] + lo2f(rhv) + lo2f(rlv), 0.f);
                    float v1 = fmaxf(a2[half][mt][nt][h * 2 + 1] + hi2f(rhv) + hi2f(rlv), 0.f);
                    uint32_t hv = packbf(v0, v1);
                    uint32_t lv = packbf(v0 - lo2f(hv), v1 - hi2f(hv));
                    *(uint32_t*)(oh + (size_t)p * 128 + col) = hv;
                    *(uint32_t*)(ol + (size_t)p * 128 + col) = lv;
                }
    }
}

// ------------------------------ fc1 (512 thr) -------------------------------
// t[branch] = relu( src @ W1[layer] ), K=128, both chunks prefetched (96KB).
// 16 warps of m32 x n16 (4m x 4n over N=64) -> 32 warps/SM at 2 CTA/SM.
__global__ void __launch_bounds__(512, 2)
fc1_kernel(int unit) {
    uint32_t sb = smem_u32(dsm);
    int tid = threadIdx.x, lane = tid & 31, wid = tid >> 5;
    int p0 = blockIdx.x * 128;
    int branch = blockIdx.y;
    int layer = unit + 3 * branch;
    int m0 = (wid & 3) * 32, n0w = (wid >> 2) * 16;
    const __nv_bfloat16* sh = (unit == 0) ? xp_hi : ab_hi[branch];
    const __nv_bfloat16* sl = (unit == 0) ? xp_lo : ab_lo[branch];
    const __nv_bfloat16* wh = w1t_hi + (size_t)layer * 8192;
    const __nv_bfloat16* wl = w1t_lo + (size_t)layer * 8192;
    float acc[2][2][4] = {};

    stageA_planes512(sb, sh, sl, 128, 0, p0, tid);
    stageB512(sb + OF_BH, wh, wl, 128, 0, tid);
    CP_COMMIT();
    stageA_planes512(sb + STG, sh, sl, 128, 64, p0, tid);
    stageB512(sb + STG + OF_BH, wh, wl, 128, 64, tid);
    CP_COMMIT();

    CP_WAIT(1);
    __syncthreads();
    mma_chunk16(acc, sb, sb + OF_AL, sb + OF_BH, sb + OF_BL, m0, n0w, lane);
    CP_WAIT(0);
    __syncthreads();
    {
        uint32_t S = sb + STG;
        mma_chunk16(acc, S, S + OF_AL, S + OF_BH, S + OF_BL, m0, n0w, lane);
    }
    epi_planes16(acc, t_hi[branch], t_lo[branch], 64, 0, p0, m0, n0w, lane);
}

// ------------------------------ final (512 thr) -----------------------------
// out = a * sigmoid(b @ Wf) + x, K=128 both chunks prefetched, N via blockIdx.y
__global__ void __launch_bounds__(512, 2)
final_kernel(const float* __restrict__ x, float* __restrict__ out) {
    uint32_t sb = smem_u32(dsm);
    int tid = threadIdx.x, lane = tid & 31, wid = tid >> 5;
    int p0 = blockIdx.x * 128, cb = blockIdx.y * 64;
    int m0 = (wid & 3) * 32, n0w = (wid >> 2) * 16;
    const __nv_bfloat16* wh = wft_hi + (size_t)cb * 128;
    const __nv_bfloat16* wl = wft_lo + (size_t)cb * 128;
    float acc[2][2][4] = {};

    stageA_planes512(sb, ab_hi[1], ab_lo[1], 128, 0, p0, tid);
    stageB512(sb + OF_BH, wh, wl, 128, 0, tid);
    CP_COMMIT();
    stageA_planes512(sb + STG, ab_hi[1], ab_lo[1], 128, 64, p0, tid);
    stageB512(sb + STG + OF_BH, wh, wl, 128, 64, tid);
    CP_COMMIT();

    CP_WAIT(1);
    __syncthreads();
    mma_chunk16(acc, sb, sb + OF_AL, sb + OF_BH, sb + OF_BL, m0, n0w, lane);
    CP_WAIT(0);
    __syncthreads();
    {
        uint32_t S = sb + STG;
        mma_chunk16(acc, S, S + OF_AL, S + OF_BH, S + OF_BL, m0, n0w, lane);
    }

    int r0 = lane >> 2, c0 = (lane & 3) << 1;
#pragma unroll
    for (int mt = 0; mt < 2; ++mt)
#pragma unroll
        for (int nt = 0; nt < 2; ++nt)
#pragma unroll
            for (int h = 0; h < 2; ++h) {
                int p = p0 + m0 + mt * 16 + r0 + h * 8;
                if (p >= NPTS) continue;
                int col = cb + n0w + nt * 8 + c0;
                uint32_t ahv = *(const uint32_t*)(ab_hi[0] + (size_t)p * 128 + col);
                uint32_t alv = *(const uint32_t*)(ab_lo[0] + (size_t)p * 128 + col);
                float a0 = lo2f(ahv) + lo2f(alv), a1 = hi2f(ahv) + hi2f(alv);
                float2 xv = *(const float2*)(x + (size_t)p * 128 + col);
                float g0 = acc[mt][nt][h * 2 + 0], g1 = acc[mt][nt][h * 2 + 1];
                float2 v;
                v.x = a0 * (1.f / (1.f + __expf(-g0))) + xv.x;
                v.y = a1 * (1.f / (1.f + __expf(-g1))) + xv.y;
                *(float2*)(out + (size_t)p * 128 + col) = v;
            }
}

// ---------------------------------------------------------------------------
extern "C" void kernel_launch(void* const* d_in, const int* in_sizes, int n_in,
                              void* d_out, int out_size) {
    const float* x   = (const float*)d_in[0];
    const float* W1s = (const float*)d_in[1];
    const float* Wks = (const float*)d_in[2];
    const float* W2s = (const float*)d_in[3];
    const float* Wf  = (const float*)d_in[4];
    const int*   nbr = (const int*)d_in[5];
    float*       out = (float*)d_out;

    const int SM_BIG = 2 * STG;   // 98304 -> 2 CTA/SM everywhere

    cudaFuncSetAttribute(conv_fc2_kernel, cudaFuncAttributeMaxDynamicSharedMemorySize, SM_BIG);
    cudaFuncSetAttribute(fc1_kernel,      cudaFuncAttributeMaxDynamicSharedMemorySize, SM_BIG);
    cudaFuncSetAttribute(final_kernel,    cudaFuncAttributeMaxDynamicSharedMemorySize, SM_BIG);

    prep_w<<<3040, 256>>>(W1s, Wks, W2s, Wf);
    prep_x<<<(NPTS * 128 / 4 + 255) / 256, 256>>>(x);

    dim3 blk512(512);
    dim3 g2(NBLK, 2);

    for (int i = 0; i < 3; ++i) {
        fc1_kernel<<<g2, blk512, SM_BIG>>>(i);
        conv_fc2_kernel<<<g2, blk512, SM_BIG>>>(nbr, i);
    }
    final_kernel<<<g2, blk512, SM_BIG>>>(x, out);
}